// round 12
// baseline (speedup 1.0000x reference)
#include <cuda_runtime.h>
#include <cuda_fp16.h>
#include <math.h>
#include <stdint.h>
#include <cstdint>

#define NQ 2048
#define NW 64
#define DD 512
#define D2 1024
#define TEMP_SC 16.0f
#define LN_EPS 1e-5f

// ---------------- scratch ----------------
__device__ float g_Q1[NQ * DD];
__device__ float g_C1[NW * DD];
__device__ float g_QW[NQ * DD];        // Q1 @ w2
__device__ float g_s1[DD];
__device__ float g_bb[DD];
__device__ float g_s1w[DD];            // s1 @ w2
__device__ float g_bbw[DD];            // bb @ w2
__device__ float g_qsum[NQ];
__device__ float g_qssq[NQ];
__device__ float g_csum[NW];
__device__ float g_cssq[NW];
__device__ float g_chatT[DD * NW];     // [j][w]
__device__ float g_swc[NW];
__device__ float g_sbc[NW];
__device__ float g_scal[3];
__device__ __align__(128) __half g_w2th[DD * DD];  // w2^T [j][k] fp16
__device__ __align__(128) __half g_c1h[NW * DD];   // C1 fp16 [w][j]
__device__ __align__(128) __half g_cwh[DD * NW];   // 0.5*CW^T fp16 [j][w']

#define SWZ(o) ((o) ^ (((o) >> 3) & 0x70))

// ================= helpers =================
__device__ __forceinline__ uint32_t smem_u32(const void* p) {
    uint32_t a;
    asm("{ .reg .u64 t; cvta.to.shared.u64 t, %1; cvt.u32.u64 %0, t; }" : "=r"(a) : "l"(p));
    return a;
}
__device__ __forceinline__ void cp16(uint32_t s, const void* g) {
    asm volatile("cp.async.cg.shared.global [%0], [%1], 16;" :: "r"(s), "l"(g));
}
__device__ __forceinline__ void ldsm4(uint32_t* r, uint32_t a) {
    asm volatile("ldmatrix.sync.aligned.m8n8.x4.shared.b16 {%0,%1,%2,%3}, [%4];"
                 : "=r"(r[0]), "=r"(r[1]), "=r"(r[2]), "=r"(r[3]) : "r"(a));
}
__device__ __forceinline__ void mma16816h(float* d, const uint32_t* a, const uint32_t* b) {
    asm volatile("mma.sync.aligned.m16n8k16.row.col.f32.f16.f16.f32 "
                 "{%0,%1,%2,%3}, {%4,%5,%6,%7}, {%8,%9}, {%0,%1,%2,%3};"
                 : "+f"(d[0]), "+f"(d[1]), "+f"(d[2]), "+f"(d[3])
                 : "r"(a[0]), "r"(a[1]), "r"(a[2]), "r"(a[3]), "r"(b[0]), "r"(b[1]));
}

// ================= phase A =================
// merged stats: blocks [0,2048)=q rowstats; [2048,2112)=class prep; 2112=ln2 scalars
__global__ void k_stats(const float* __restrict__ q, const float* __restrict__ cm,
                        const float* __restrict__ ln2w, const float* __restrict__ ln2b) {
    int b = blockIdx.x, tid = threadIdx.x;
    int lane = tid & 31, wid = tid >> 5;
    if (b < NQ) {
        float s = 0.f, ss = 0.f;
        for (int j = tid; j < DD; j += 256) { float v = q[b * DD + j]; s += v; ss += v * v; }
        __shared__ float sA[8], sB[8];
#pragma unroll
        for (int o = 16; o; o >>= 1) {
            s  += __shfl_down_sync(0xffffffffu, s, o);
            ss += __shfl_down_sync(0xffffffffu, ss, o);
        }
        if (lane == 0) { sA[wid] = s; sB[wid] = ss; }
        __syncthreads();
        if (tid == 0) {
            float a = 0.f, bb = 0.f;
#pragma unroll
            for (int i = 0; i < 8; i++) { a += sA[i]; bb += sB[i]; }
            g_qsum[b] = a; g_qssq[b] = bb;
        }
        return;
    }
    if (b < 2112) {
        int w = b - 2048;
        float s = 0.f, ss = 0.f, sw = 0.f, sb = 0.f;
        for (int j = tid; j < DD; j += 256) {
            float v = cm[w * DD + j];
            s += v; ss += v * v; sw += ln2w[j] * v; sb += ln2b[j] * v;
        }
        __shared__ float sA[8], sB[8], sC[8], sD[8];
        __shared__ float rbc;
#pragma unroll
        for (int o = 16; o; o >>= 1) {
            s  += __shfl_down_sync(0xffffffffu, s,  o);
            ss += __shfl_down_sync(0xffffffffu, ss, o);
            sw += __shfl_down_sync(0xffffffffu, sw, o);
            sb += __shfl_down_sync(0xffffffffu, sb, o);
        }
        if (lane == 0) { sA[wid] = s; sB[wid] = ss; sC[wid] = sw; sD[wid] = sb; }
        __syncthreads();
        if (tid == 0) {
            float a = 0.f, bb = 0.f, c = 0.f, d = 0.f;
#pragma unroll
            for (int i = 0; i < 8; i++) { a += sA[i]; bb += sB[i]; c += sC[i]; d += sD[i]; }
            g_csum[w] = a; g_cssq[w] = bb;
            float r = 1.f / fmaxf(sqrtf(bb), 1e-12f);
            rbc = r; g_swc[w] = r * c; g_sbc[w] = r * d;
        }
        __syncthreads();
        float r = rbc;
        for (int j = tid; j < DD; j += 256)
            g_chatT[j * NW + w] = cm[w * DD + j] * r;
        return;
    }
    {
        float a = 0.f, bb = 0.f, c = 0.f;
        for (int j = tid; j < DD; j += 256) {
            float w = ln2w[j], z = ln2b[j];
            a += w * w; bb += w * z; c += z * z;
        }
        __shared__ float sA[8], sB[8], sC[8];
#pragma unroll
        for (int o = 16; o; o >>= 1) {
            a  += __shfl_down_sync(0xffffffffu, a,  o);
            bb += __shfl_down_sync(0xffffffffu, bb, o);
            c  += __shfl_down_sync(0xffffffffu, c,  o);
        }
        if (lane == 0) { sA[wid] = a; sB[wid] = bb; sC[wid] = c; }
        __syncthreads();
        if (tid == 0) {
            float x = 0.f, y = 0.f, z = 0.f;
#pragma unroll
            for (int i = 0; i < 8; i++) { x += sA[i]; y += sB[i]; z += sC[i]; }
            g_scal[0] = x; g_scal[1] = y; g_scal[2] = z;
        }
    }
}

// column-weighted sums
__global__ void k_colsum(const float* __restrict__ W, int R,
                         const float* __restrict__ va, const float* __restrict__ vb,
                         const float* __restrict__ addb,
                         float* __restrict__ oa, float* __restrict__ ob) {
    __shared__ float sa[16][17], sbm[16][17];
    int jl = threadIdx.x & 15, ti = threadIdx.x >> 4;
    int j = blockIdx.x * 16 + jl;
    float a = 0.f, b = 0.f;
    for (int i = ti; i < R; i += 16) {
        float wv = W[i * DD + j];
        a += va[i] * wv; b += vb[i] * wv;
    }
    sa[ti][jl] = a; sbm[ti][jl] = b;
    __syncthreads();
    if (ti == 0) {
#pragma unroll
        for (int k = 1; k < 16; k++) { a += sa[k][jl]; b += sbm[k][jl]; }
        oa[j] = a;
        ob[j] = (addb ? addb[j] : 0.f) + b;
    }
}

// w2 transpose to fp16 [j][k]
__global__ void k_w2h(const float* __restrict__ w2) {
    __shared__ float t[32][33];
    int bx = blockIdx.x * 32, by = blockIdx.y * 32;
    int tx = threadIdx.x, ty = threadIdx.y;
#pragma unroll
    for (int i = 0; i < 4; i++)
        t[ty + i * 8][tx] = w2[(by + ty + i * 8) * DD + bx + tx];
    __syncthreads();
#pragma unroll
    for (int i = 0; i < 4; i++) {
        int j = bx + ty + i * 8, k = by + tx;
        g_w2th[j * DD + k] = __float2half(t[tx][ty + i * 8]);
    }
}

// fold GEMM, 64x128 tiles, 4x8/thread: bx<32 -> Q1; bx==32 -> C1 fp32+fp16
__global__ void k_gemm_fold3(const float* __restrict__ q, const float* __restrict__ cm,
                             const float* __restrict__ w1, const float* __restrict__ lnw,
                             float* __restrict__ Q1, float* __restrict__ C1) {
    __shared__ __align__(16) float As[16][68];
    __shared__ __align__(16) float Bs[16][128];
    int bx = blockIdx.x;
    const float* A; int m0, rowoff;
    if (bx < 32) { A = q; m0 = bx * 64; rowoff = 0; }
    else         { A = cm; m0 = 0; rowoff = 512; }
    int j0 = blockIdx.y * 128;
    int tid = threadIdx.x;
    int tr = tid >> 4, tc = tid & 15;
    int r0 = tr * 4, c0 = tc * 8;
    float acc[4][8] = {};
    for (int kc = 0; kc < DD; kc += 16) {
        __syncthreads();
#pragma unroll
        for (int e = 0; e < 4; e++) {
            int idx = tid + e * 256;
            int m = idx >> 4, kk = idx & 15;
            As[kk][m] = A[(m0 + m) * DD + kc + kk] * lnw[rowoff + kc + kk];
        }
#pragma unroll
        for (int e = 0; e < 8; e++) {
            int idx = tid + e * 256;
            int kk = idx >> 7, j = idx & 127;
            Bs[kk][j] = w1[(rowoff + kc + kk) * DD + j0 + j];
        }
        __syncthreads();
#pragma unroll
        for (int kk = 0; kk < 16; kk++) {
            float4 av = *(const float4*)&As[kk][r0];
            float4 b0 = *(const float4*)&Bs[kk][c0];
            float4 b1 = *(const float4*)&Bs[kk][c0 + 4];
            float a4[4] = {av.x, av.y, av.z, av.w};
            float b8[8] = {b0.x, b0.y, b0.z, b0.w, b1.x, b1.y, b1.z, b1.w};
#pragma unroll
            for (int i = 0; i < 4; i++)
#pragma unroll
                for (int j = 0; j < 8; j++)
                    acc[i][j] += a4[i] * b8[j];
        }
    }
    if (bx < 32) {
#pragma unroll
        for (int i = 0; i < 4; i++)
#pragma unroll
            for (int j = 0; j < 8; j++)
                Q1[(m0 + r0 + i) * DD + j0 + c0 + j] = acc[i][j];
    } else {
#pragma unroll
        for (int i = 0; i < 4; i++)
#pragma unroll
            for (int j = 0; j < 8; j++) {
                int idx = (r0 + i) * DD + j0 + c0 + j;
                C1[idx] = acc[i][j];
                g_c1h[idx] = __float2half(acc[i][j]);
            }
    }
}

// plain GEMM vs w2, 64x128 tiles: bx<32 -> QW; bx==32 -> g_cwh (0.5x, transposed)
__global__ void k_gemm_plain3(const float* __restrict__ Q1, const float* __restrict__ C1,
                              const float* __restrict__ w2, float* __restrict__ QW) {
    __shared__ __align__(16) float As[16][68];
    __shared__ __align__(16) float Bs[16][128];
    int bx = blockIdx.x;
    const float* A; int m0;
    if (bx < 32) { A = Q1; m0 = bx * 64; }
    else         { A = C1; m0 = 0; }
    int j0 = blockIdx.y * 128;
    int tid = threadIdx.x;
    int tr = tid >> 4, tc = tid & 15;
    int r0 = tr * 4, c0 = tc * 8;
    float acc[4][8] = {};
    for (int kc = 0; kc < DD; kc += 16) {
        __syncthreads();
#pragma unroll
        for (int e = 0; e < 4; e++) {
            int idx = tid + e * 256;
            int m = idx >> 4, kk = idx & 15;
            As[kk][m] = A[(m0 + m) * DD + kc + kk];
        }
#pragma unroll
        for (int e = 0; e < 8; e++) {
            int idx = tid + e * 256;
            int kk = idx >> 7, j = idx & 127;
            Bs[kk][j] = w2[(kc + kk) * DD + j0 + j];
        }
        __syncthreads();
#pragma unroll
        for (int kk = 0; kk < 16; kk++) {
            float4 av = *(const float4*)&As[kk][r0];
            float4 b0 = *(const float4*)&Bs[kk][c0];
            float4 b1 = *(const float4*)&Bs[kk][c0 + 4];
            float a4[4] = {av.x, av.y, av.z, av.w};
            float b8[8] = {b0.x, b0.y, b0.z, b0.w, b1.x, b1.y, b1.z, b1.w};
#pragma unroll
            for (int i = 0; i < 4; i++)
#pragma unroll
                for (int j = 0; j < 8; j++)
                    acc[i][j] += a4[i] * b8[j];
        }
    }
    if (bx < 32) {
#pragma unroll
        for (int i = 0; i < 4; i++)
#pragma unroll
            for (int j = 0; j < 8; j++)
                QW[(m0 + r0 + i) * DD + j0 + c0 + j] = acc[i][j];
    } else {
#pragma unroll
        for (int i = 0; i < 4; i++)
#pragma unroll
            for (int j = 0; j < 8; j++)
                g_cwh[(j0 + c0 + j) * NW + (r0 + i)] = __float2half(0.5f * acc[i][j]);
    }
}

// ================= main HMMA kernel: K=512, CW in epilogue, build overlapped =================
#define OFF_A    0          // 8 x 16384 = 131072
#define OFF_B    131072     // 2 x 16384 = 32768
#define OFF_CHAT 163840     // 34816: chat chunk (stride 272B); red at end
#define OFF_CWH  198656     // 18432: cwh chunk (fp16, stride 144B = 72 halves)
#define OFF_META 217088
#define M_MU   0
#define M_IV   128
#define M_U1   256
#define M_U2   768    // [2][512]
#define M_U3   1792   // [2][512]
#define M_LW   2816
#define M_LB   3328
#define SMEM_TC 232448   // == 227 KB opt-in cap

__device__ __forceinline__ void cp_chat(uint32_t sb, int ch, int tid) {
    int j0 = ch * 128;
#pragma unroll
    for (int i = 0; i < 8; i++) {
        int u = tid + i * 256;
        int row = u >> 4, c16 = u & 15;
        cp16(sb + OFF_CHAT + (uint32_t)(row * 272 + c16 * 16),
             (const char*)g_chatT + (size_t)(j0 + row) * 256 + c16 * 16);
    }
#pragma unroll
    for (int i = 0; i < 4; i++) {
        int u = tid + i * 256;
        int row = u >> 3, c16 = u & 7;
        cp16(sb + OFF_CWH + (uint32_t)(row * 144 + c16 * 16),
             (const char*)g_cwh + (size_t)(j0 + row) * 128 + c16 * 16);
    }
}

// load B tile t (t = ch*8 + kc); kc==1 piggybacks chat+cwh(ch)
__device__ __forceinline__ void cp_B(uint32_t sb, int t, int tid) {
    int ch = t >> 3, kc = t & 7;
    int j0 = ch * 128;
    uint32_t bh = sb + OFF_B + (t & 1) * 16384;
    const char* gh = (const char*)g_w2th + (size_t)j0 * 1024 + (size_t)kc * 128;
#pragma unroll
    for (int i = 0; i < 4; i++) {
        int u = tid + i * 256;
        int row = u >> 3, c16 = u & 7;
        uint32_t o = (uint32_t)(row * 128 + c16 * 16);
        cp16(bh + SWZ(o), gh + (size_t)row * 1024 + c16 * 16);
    }
    if (kc == 1) cp_chat(sb, ch, tid);
    asm volatile("cp.async.commit_group;" ::: "memory");
}

// build residual A subtile kc from L2-resident globals: 0.5*h*erf(h/sqrt2), fp16
__device__ __forceinline__ void buildA(char* smem, int kc, int tid,
                                       const float* meta, int n0) {
    int r = tid >> 1, w = r & 63, rn = r >> 6;
    int kh = (tid & 1) * 32;
    float mu = meta[M_MU + r], iv = meta[M_IV + r];
    const float* Q1p = g_Q1 + (size_t)(n0 + rn) * DD + kc * 64 + kh;
    const float* s1p = g_s1 + kc * 64 + kh;
    const float* bbp = g_bb + kc * 64 + kh;
    const __half* c1p = g_c1h + (size_t)w * DD + kc * 64 + kh;
    char* ah = smem + OFF_A + kc * 16384;
#pragma unroll
    for (int kk = 0; kk < 32; kk += 2) {
        float2 qv = *(const float2*)(Q1p + kk);
        float2 sv = *(const float2*)(s1p + kk);
        float2 bv = *(const float2*)(bbp + kk);
        float2 cf = __half22float2(*(const __half2*)(c1p + kk));
        float ha = iv * (qv.x + cf.x - mu * sv.x) + bv.x;
        float hb = iv * (qv.y + cf.y - mu * sv.y) + bv.y;
        float ga = 0.5f * ha * erff(ha * 0.70710678118654752f);
        float gb = 0.5f * hb * erff(hb * 0.70710678118654752f);
        __half2 hp = __floats2half2_rn(ga, gb);
        uint32_t o = (uint32_t)(r * 128 + (kh + kk) * 2);
        *(__half2*)(ah + SWZ(o)) = hp;
    }
}

__global__ void __launch_bounds__(256, 1)
k_tc7(const float* __restrict__ q, const float* __restrict__ b2,
      const float* __restrict__ ln2w, const float* __restrict__ ln2b,
      float* __restrict__ out) {
    extern __shared__ char smem[];
    const uint32_t sb = smem_u32(smem);
    const int tid = threadIdx.x, lane = tid & 31, wid = tid >> 5;
    const int pair = blockIdx.x;
    const int n0 = pair * 2;
    float* meta = (float*)(smem + OFF_META);
    float* chs = (float*)(smem + OFF_CHAT);
    const __half* cwhs = (const __half*)(smem + OFF_CWH);

    // ---- prologue: meta ----
    for (int j = tid; j < DD; j += 256) {
        meta[M_U1 + j] = 0.5f * g_s1w[j];
        meta[M_U2 + j]       = 0.5f * g_QW[n0 * DD + j];
        meta[M_U2 + 512 + j] = 0.5f * g_QW[(n0 + 1) * DD + j];
        float hb = b2[j] + 0.5f * g_bbw[j];
        meta[M_U3 + j]       = q[n0 * DD + j] + hb;
        meta[M_U3 + 512 + j] = q[(n0 + 1) * DD + j] + hb;
        meta[M_LW + j] = ln2w[j];
        meta[M_LB + j] = ln2b[j];
    }
    if (tid < 128) {
        int rn = tid >> 6, w = tid & 63;
        float sx  = g_qsum[n0 + rn] + g_csum[w];
        float sxx = g_qssq[n0 + rn] + g_cssq[w];
        float m = sx * (1.f / 1024.f);
        float var = sxx * (1.f / 1024.f) - m * m;
        meta[M_MU + tid] = m;
        meta[M_IV + tid] = rsqrtf(var + LN_EPS);
    }
    __syncthreads();

    // ---- build A[0]; stage chat/cwh(0) + B tile 0 ----
    buildA(smem, 0, tid, meta, n0);
    cp_chat(sb, 0, tid);
    cp_B(sb, 0, tid);
    __syncthreads();

    // ---- mainloop: 4 chunks x 8 kc ----
    const int wm = wid & 3, wn = wid >> 2;
    const int arow = ((lane >> 3) & 1) * 8 + (lane & 7);
    const int acol = lane >> 4;
    const int brow = (lane >> 4) * 8 + (lane & 7);
    const int bcol = (lane >> 3) & 1;
    const int qr = lane >> 2, qc = lane & 3;

    float d[16][4];
#pragma unroll
    for (int i = 0; i < 16; i++)
#pragma unroll
        for (int j = 0; j < 4; j++) d[i][j] = 0.f;
    float pm[4][6];
#pragma unroll
    for (int i = 0; i < 4; i++)
#pragma unroll
        for (int m = 0; m < 6; m++) pm[i][m] = 0.f;

    for (int t = 0; t < 32; t++) {
        const int ch = t >> 3, kc = t & 7;
        if (t < 31) cp_B(sb, t + 1, tid);
        if (t < 31) { asm volatile("cp.async.wait_group 1;" ::: "memory"); }
        else        { asm volatile("cp.async.wait_group 0;" ::: "memory"); }
        __syncthreads();
        uint32_t Ah = sb + OFF_A + kc * 16384;
        uint32_t Bh = sb + OFF_B + (t & 1) * 16384;
#pragma unroll
        for (int s = 0; s < 4; s++) {
            uint32_t ahi[2][4], bhi[4][4];
#pragma unroll
            for (int tm = 0; tm < 2; tm++) {
                uint32_t o = (uint32_t)((32 * wm + 16 * tm + arow) * 128 + (2 * s + acol) * 16);
                ldsm4(ahi[tm], Ah + SWZ(o));
            }
#pragma unroll
            for (int u = 0; u < 4; u++) {
                uint32_t o = (uint32_t)((64 * wn + 16 * u + brow) * 128 + (2 * s + bcol) * 16);
                ldsm4(bhi[u], Bh + SWZ(o));
            }
#pragma unroll
            for (int tm = 0; tm < 2; tm++)
#pragma unroll
                for (int u = 0; u < 4; u++) {
                    mma16816h(d[tm * 8 + 2 * u],     ahi[tm], &bhi[u][0]);
                    mma16816h(d[tm * 8 + 2 * u + 1], ahi[tm], &bhi[u][2]);
                }
        }
        // overlap: gelu-build of next A subtile while tensor pipe drains
        if (ch == 0 && kc < 7) buildA(smem, kc + 1, tid, meta, n0);
        __syncthreads();

        if (kc == 7) {
            const int j0 = ch * 128;
#pragma unroll
            for (int tm = 0; tm < 2; tm++)
#pragma unroll
                for (int h = 0; h < 2; h++) {
                    int row = 32 * wm + 16 * tm + 8 * h + qr;
                    int w = row & 63, rn = row >> 6;
                    float ivr = meta[M_IV + row];
                    float a = -ivr * meta[M_MU + row];
                    float p0 = 0.f, p1 = 0.f, pA = 0.f, pB = 0.f, pC = 0.f, pE = 0.f;
#pragma unroll
                    for (int nt = 0; nt < 8; nt++) {
                        int cl0 = 64 * wn + 8 * nt + qc * 2;
                        int col0 = j0 + cl0;
                        float2 U1 = *(const float2*)&meta[M_U1 + col0];
                        float2 U2 = *(const float2*)&meta[M_U2 + rn * 512 + col0];
                        float2 U3 = *(const float2*)&meta[M_U3 + rn * 512 + col0];
                        float2 LWv = *(const float2*)&meta[M_LW + col0];
                        float2 LBv = *(const float2*)&meta[M_LB + col0];
                        float ch0 = chs[cl0 * 68 + w];
                        float ch1 = chs[(cl0 + 1) * 68 + w];
                        float cw0 = __half2float(cwhs[cl0 * 72 + w]);
                        float cw1 = __half2float(cwhs[(cl0 + 1) * 72 + w]);
                        float v0 = d[tm * 8 + nt][h * 2]     + a * U1.x + ivr * (U2.x + cw0) + U3.x;
                        float v1 = d[tm * 8 + nt][h * 2 + 1] + a * U1.y + ivr * (U2.y + cw1) + U3.y;
                        float vw0 = v0 * LWv.x, vw1 = v1 * LWv.y;
                        p0 += v0 + v1;
                        p1 += v0 * v0 + v1 * v1;
                        pA += vw0 * ch0 + vw1 * ch1;
                        pB += vw0 * vw0 + vw1 * vw1;
                        pC += vw0 * LWv.x + vw1 * LWv.y;
                        pE += vw0 * LBv.x + vw1 * LBv.y;
                    }
                    int i = tm * 2 + h;
                    pm[i][0] += p0; pm[i][1] += p1; pm[i][2] += pA;
                    pm[i][3] += pB; pm[i][4] += pC; pm[i][5] += pE;
                }
            if (t < 31) {
#pragma unroll
                for (int i = 0; i < 16; i++)
#pragma unroll
                    for (int j = 0; j < 4; j++) d[i][j] = 0.f;
            }
        }
    }

    // ---- final reduce (red aliases CHAT region) ----
    __syncthreads();
    float* sred = (float*)(smem + OFF_CHAT);
#pragma unroll
    for (int tm = 0; tm < 2; tm++)
#pragma unroll
        for (int h = 0; h < 2; h++) {
            int i = tm * 2 + h;
            int row = 32 * wm + 16 * tm + 8 * h + qr;
#pragma unroll
            for (int o = 1; o <= 2; o <<= 1)
#pragma unroll
                for (int m = 0; m < 6; m++)
                    pm[i][m] += __shfl_down_sync(0xffffffffu, pm[i][m], o, 4);
            if (qc == 0) {
                float* rp = sred + (wn * 128 + row) * 8;
#pragma unroll
                for (int m = 0; m < 6; m++) rp[m] = pm[i][m];
            }
        }
    __syncthreads();
    if (tid < 128) {
        int row = tid, w = row & 63, nn = n0 + (row >> 6);
        float m0 = sred[row * 8 + 0] + sred[(128 + row) * 8 + 0];
        float m1 = sred[row * 8 + 1] + sred[(128 + row) * 8 + 1];
        float A  = sred[row * 8 + 2] + sred[(128 + row) * 8 + 2];
        float B  = sred[row * 8 + 3] + sred[(128 + row) * 8 + 3];
        float C  = sred[row * 8 + 4] + sred[(128 + row) * 8 + 4];
        float E  = sred[row * 8 + 5] + sred[(128 + row) * 8 + 5];
        float mu2 = m0 * (1.f / DD);
        float var = m1 * (1.f / DD) - mu2 * mu2;
        float k = rsqrtf(var + LN_EPS);
        float sww = g_scal[0], swb = g_scal[1], sbb = g_scal[2];
        float doty = k * (A - mu2 * g_swc[w]) + g_sbc[w];
        float ny2 = k * k * (B - 2.f * mu2 * C + mu2 * mu2 * sww)
                  + 2.f * k * (E - mu2 * swb) + sbb;
        float ny = sqrtf(fmaxf(ny2, 0.f));
        out[nn * NW + w] = TEMP_SC * doty / fmaxf(ny, 1e-12f);
    }
}

// ================= launch =================
extern "C" void kernel_launch(void* const* d_in, const int* in_sizes, int n_in,
                              void* d_out, int out_size) {
    const float* q    = (const float*)d_in[0];
    const float* cm   = (const float*)d_in[1];
    const float* ln1w = (const float*)d_in[2];
    const float* ln1b = (const float*)d_in[3];
    const float* w1   = (const float*)d_in[4];
    const float* b1   = (const float*)d_in[5];
    const float* w2   = (const float*)d_in[6];
    const float* b2   = (const float*)d_in[7];
    const float* ln2w = (const float*)d_in[8];
    const float* ln2b = (const float*)d_in[9];
    float* out = (float*)d_out;

    float *pQ1, *pC1, *pQW, *pS1, *pBB, *pS1W, *pBBW;
    cudaGetSymbolAddress((void**)&pQ1, g_Q1);
    cudaGetSymbolAddress((void**)&pC1, g_C1);
    cudaGetSymbolAddress((void**)&pQW, g_QW);
    cudaGetSymbolAddress((void**)&pS1, g_s1);
    cudaGetSymbolAddress((void**)&pBB, g_bb);
    cudaGetSymbolAddress((void**)&pS1W, g_s1w);
    cudaGetSymbolAddress((void**)&pBBW, g_bbw);

    cudaFuncSetAttribute(k_tc7, cudaFuncAttributeMaxDynamicSharedMemorySize, SMEM_TC);

    k_stats<<<2113, 256>>>(q, cm, ln2w, ln2b);
    k_w2h<<<dim3(16, 16), dim3(32, 8)>>>(w2);
    k_colsum<<<32, 256>>>(w1, D2, ln1w, ln1b, b1, pS1, pBB);
    k_gemm_fold3<<<dim3(33, 4), 256>>>(q, cm, w1, ln1w, pQ1, pC1);
    k_colsum<<<32, 256>>>(w2, DD, pS1, pBB, (const float*)nullptr, pS1W, pBBW);
    k_gemm_plain3<<<dim3(33, 4), 256>>>(pQ1, pC1, w2, pQW);
    k_tc7<<<NQ / 2, 256, SMEM_TC>>>(q, b2, ln2w, ln2b, out);
}

// round 13
// speedup vs baseline: 1.0903x; 1.0903x over previous
#include <cuda_runtime.h>
#include <cuda_fp16.h>
#include <math.h>
#include <stdint.h>
#include <cstdint>

#define NQ 2048
#define NW 64
#define DD 512
#define D2 1024
#define TEMP_SC 16.0f
#define LN_EPS 1e-5f

// ---------------- scratch ----------------
__device__ float g_Q1[NQ * DD];
__device__ float g_C1[NW * DD];
__device__ float g_QW[NQ * DD];        // Q1 @ w2
__device__ float g_s1[DD];
__device__ float g_bb[DD];
__device__ float g_s1w[DD];            // s1 @ w2
__device__ float g_bbw[DD];            // bb @ w2
__device__ float g_qsum[NQ];
__device__ float g_qssq[NQ];
__device__ float g_csum[NW];
__device__ float g_cssq[NW];
__device__ float g_chatT[DD * NW];     // [j][w]
__device__ float g_swc[NW];
__device__ float g_sbc[NW];
__device__ float g_scal[3];
__device__ __align__(128) __half g_w2th[DD * DD];  // w2^T [j][k] fp16
__device__ __align__(128) __half g_c1h[NW * DD];   // C1 fp16 [w][j]
__device__ __align__(128) __half g_cwh[DD * NW];   // 0.5*CW^T fp16 [j][w']

#define SWZ(o) ((o) ^ (((o) >> 3) & 0x70))

// ================= helpers =================
__device__ __forceinline__ uint32_t smem_u32(const void* p) {
    uint32_t a;
    asm("{ .reg .u64 t; cvta.to.shared.u64 t, %1; cvt.u32.u64 %0, t; }" : "=r"(a) : "l"(p));
    return a;
}
__device__ __forceinline__ void cp16(uint32_t s, const void* g) {
    asm volatile("cp.async.cg.shared.global [%0], [%1], 16;" :: "r"(s), "l"(g));
}
__device__ __forceinline__ void ldsm4(uint32_t* r, uint32_t a) {
    asm volatile("ldmatrix.sync.aligned.m8n8.x4.shared.b16 {%0,%1,%2,%3}, [%4];"
                 : "=r"(r[0]), "=r"(r[1]), "=r"(r[2]), "=r"(r[3]) : "r"(a));
}
__device__ __forceinline__ void mma16816h(float* d, const uint32_t* a, const uint32_t* b) {
    asm volatile("mma.sync.aligned.m16n8k16.row.col.f32.f16.f16.f32 "
                 "{%0,%1,%2,%3}, {%4,%5,%6,%7}, {%8,%9}, {%0,%1,%2,%3};"
                 : "+f"(d[0]), "+f"(d[1]), "+f"(d[2]), "+f"(d[3])
                 : "r"(a[0]), "r"(a[1]), "r"(a[2]), "r"(a[3]), "r"(b[0]), "r"(b[1]));
}

// shared GEMM inner body (64x64 tile, 4x4/thread, float4 smem reads) — R11-proven
struct GemmSmem {
    __align__(16) float As[16][68];
    __align__(16) float Bs[16][64];
};

__device__ __forceinline__ void gemm_body(GemmSmem* gs, const float* A, int m0,
                                          const float* B, int browoff, int j0,
                                          const float* lnw, int lnoff, bool useln,
                                          int tid, float acc[4][4]) {
    int tr = tid >> 4, tc = tid & 15;
    int r0 = tr * 4, c0 = tc * 4;
    for (int kc = 0; kc < DD; kc += 16) {
        __syncthreads();
#pragma unroll
        for (int e = 0; e < 4; e++) {
            int idx = tid + e * 256;
            int m = idx >> 4, kk = idx & 15;
            float v = A[(m0 + m) * DD + kc + kk];
            if (useln) v *= lnw[lnoff + kc + kk];
            gs->As[kk][m] = v;
        }
#pragma unroll
        for (int e = 0; e < 4; e++) {
            int idx = tid + e * 256;
            int kk = idx >> 6, j = idx & 63;
            gs->Bs[kk][j] = B[(browoff + kc + kk) * DD + j0 + j];
        }
        __syncthreads();
#pragma unroll
        for (int kk = 0; kk < 16; kk++) {
            float4 av = *(const float4*)&gs->As[kk][r0];
            float4 bv = *(const float4*)&gs->Bs[kk][c0];
            acc[0][0] += av.x * bv.x; acc[0][1] += av.x * bv.y; acc[0][2] += av.x * bv.z; acc[0][3] += av.x * bv.w;
            acc[1][0] += av.y * bv.x; acc[1][1] += av.y * bv.y; acc[1][2] += av.y * bv.z; acc[1][3] += av.y * bv.w;
            acc[2][0] += av.z * bv.x; acc[2][1] += av.z * bv.y; acc[2][2] += av.z * bv.z; acc[2][3] += av.z * bv.w;
            acc[3][0] += av.w * bv.x; acc[3][1] += av.w * bv.y; acc[3][2] += av.w * bv.z; acc[3][3] += av.w * bv.w;
        }
    }
}

__device__ __forceinline__ void colsum_body(const float* W, int R,
                                            const float* va, const float* vb,
                                            const float* addb,
                                            float* oa, float* ob,
                                            int blk, int tid) {
    __shared__ float sa[16][17], sbm[16][17];
    int jl = tid & 15, ti = tid >> 4;
    int j = blk * 16 + jl;
    float a = 0.f, b = 0.f;
    for (int i = ti; i < R; i += 16) {
        float wv = W[i * DD + j];
        a += va[i] * wv; b += vb[i] * wv;
    }
    sa[ti][jl] = a; sbm[ti][jl] = b;
    __syncthreads();
    if (ti == 0) {
#pragma unroll
        for (int k = 1; k < 16; k++) { a += sa[k][jl]; b += sbm[k][jl]; }
        oa[j] = a;
        ob[j] = (addb ? addb[j] : 0.f) + b;
    }
}

// ================= phase 1: fold GEMM + stats + w2h + colsum(w1), one launch =================
// blocks [0,264): fold GEMM (33x8); [264,2377): stats; [2377,2633): w2h; [2633,2665): colsum w1
__global__ void k_phase1(const float* __restrict__ q, const float* __restrict__ cm,
                         const float* __restrict__ ln1w, const float* __restrict__ ln1b,
                         const float* __restrict__ b1, const float* __restrict__ w1,
                         const float* __restrict__ w2,
                         const float* __restrict__ ln2w, const float* __restrict__ ln2b,
                         float* __restrict__ Q1, float* __restrict__ C1) {
    int b = blockIdx.x, tid = threadIdx.x;
    int lane = tid & 31, wid = tid >> 5;

    if (b < 264) {
        __shared__ GemmSmem gs;
        int bx = b % 33, by = b / 33;
        int j0 = by * 64;
        const float* A; int m0, rowoff;
        if (bx < 32) { A = q; m0 = bx * 64; rowoff = 0; }
        else         { A = cm; m0 = 0; rowoff = 512; }
        float acc[4][4] = {};
        gemm_body(&gs, A, m0, w1, rowoff, j0, ln1w, rowoff, true, tid, acc);
        int tr = tid >> 4, tc = tid & 15;
        int r0 = tr * 4, c0 = tc * 4;
        if (bx < 32) {
#pragma unroll
            for (int i = 0; i < 4; i++)
#pragma unroll
                for (int j = 0; j < 4; j++)
                    Q1[(m0 + r0 + i) * DD + j0 + c0 + j] = acc[i][j];
        } else {
#pragma unroll
            for (int i = 0; i < 4; i++)
#pragma unroll
                for (int j = 0; j < 4; j++) {
                    int idx = (r0 + i) * DD + j0 + c0 + j;
                    C1[idx] = acc[i][j];
                    g_c1h[idx] = __float2half(acc[i][j]);
                }
        }
        return;
    }
    if (b < 2377) {
        int sbk = b - 264;
        if (sbk < NQ) {
            float s = 0.f, ss = 0.f;
            for (int j = tid; j < DD; j += 256) { float v = q[sbk * DD + j]; s += v; ss += v * v; }
            __shared__ float sA[8], sB[8];
#pragma unroll
            for (int o = 16; o; o >>= 1) {
                s  += __shfl_down_sync(0xffffffffu, s, o);
                ss += __shfl_down_sync(0xffffffffu, ss, o);
            }
            if (lane == 0) { sA[wid] = s; sB[wid] = ss; }
            __syncthreads();
            if (tid == 0) {
                float a = 0.f, bb = 0.f;
#pragma unroll
                for (int i = 0; i < 8; i++) { a += sA[i]; bb += sB[i]; }
                g_qsum[sbk] = a; g_qssq[sbk] = bb;
            }
        } else if (sbk < 2112) {
            int w = sbk - NQ;
            float s = 0.f, ss = 0.f, sw = 0.f, sb = 0.f;
            for (int j = tid; j < DD; j += 256) {
                float v = cm[w * DD + j];
                s += v; ss += v * v; sw += ln2w[j] * v; sb += ln2b[j] * v;
            }
            __shared__ float sA[8], sB[8], sC[8], sD[8];
            __shared__ float rbc;
#pragma unroll
            for (int o = 16; o; o >>= 1) {
                s  += __shfl_down_sync(0xffffffffu, s,  o);
                ss += __shfl_down_sync(0xffffffffu, ss, o);
                sw += __shfl_down_sync(0xffffffffu, sw, o);
                sb += __shfl_down_sync(0xffffffffu, sb, o);
            }
            if (lane == 0) { sA[wid] = s; sB[wid] = ss; sC[wid] = sw; sD[wid] = sb; }
            __syncthreads();
            if (tid == 0) {
                float a = 0.f, bb = 0.f, c = 0.f, d = 0.f;
#pragma unroll
                for (int i = 0; i < 8; i++) { a += sA[i]; bb += sB[i]; c += sC[i]; d += sD[i]; }
                g_csum[w] = a; g_cssq[w] = bb;
                float r = 1.f / fmaxf(sqrtf(bb), 1e-12f);
                rbc = r; g_swc[w] = r * c; g_sbc[w] = r * d;
            }
            __syncthreads();
            float r = rbc;
            for (int j = tid; j < DD; j += 256)
                g_chatT[j * NW + w] = cm[w * DD + j] * r;
        } else {
            float a = 0.f, bb = 0.f, c = 0.f;
            for (int j = tid; j < DD; j += 256) {
                float w = ln2w[j], z = ln2b[j];
                a += w * w; bb += w * z; c += z * z;
            }
            __shared__ float sA[8], sB[8], sC[8];
#pragma unroll
            for (int o = 16; o; o >>= 1) {
                a  += __shfl_down_sync(0xffffffffu, a,  o);
                bb += __shfl_down_sync(0xffffffffu, bb, o);
                c  += __shfl_down_sync(0xffffffffu, c,  o);
            }
            if (lane == 0) { sA[wid] = a; sB[wid] = bb; sC[wid] = c; }
            __syncthreads();
            if (tid == 0) {
                float x = 0.f, y = 0.f, z = 0.f;
#pragma unroll
                for (int i = 0; i < 8; i++) { x += sA[i]; y += sB[i]; z += sC[i]; }
                g_scal[0] = x; g_scal[1] = y; g_scal[2] = z;
            }
        }
        return;
    }
    if (b < 2633) {
        // w2 transpose to fp16: 16x16 grid of 32x32 tiles; threads 32x8
        __shared__ float t[32][33];
        int wb = b - 2377;
        int bx = (wb & 15) * 32, by = (wb >> 4) * 32;
        int tx = tid & 31, ty = tid >> 5;
#pragma unroll
        for (int i = 0; i < 4; i++)
            t[ty + i * 8][tx] = w2[(by + ty + i * 8) * DD + bx + tx];
        __syncthreads();
#pragma unroll
        for (int i = 0; i < 4; i++) {
            int j = bx + ty + i * 8, k = by + tx;
            g_w2th[j * DD + k] = __float2half(t[tx][ty + i * 8]);
        }
        return;
    }
    colsum_body(w1, D2, ln1w, ln1b, b1, g_s1, g_bb, b - 2633, tid);
}

// ================= phase 2: plain GEMM vs w2 + colsum(w2), one launch =================
// blocks [0,264): plain GEMM; [264,296): colsum w2
__global__ void k_phase2(const float* __restrict__ Q1, const float* __restrict__ C1,
                         const float* __restrict__ w2, float* __restrict__ QW) {
    int b = blockIdx.x, tid = threadIdx.x;
    if (b < 264) {
        __shared__ GemmSmem gs;
        int bx = b % 33, by = b / 33;
        int j0 = by * 64;
        const float* A; int m0;
        if (bx < 32) { A = Q1; m0 = bx * 64; }
        else         { A = C1; m0 = 0; }
        float acc[4][4] = {};
        gemm_body(&gs, A, m0, w2, 0, j0, (const float*)nullptr, 0, false, tid, acc);
        int tr = tid >> 4, tc = tid & 15;
        int r0 = tr * 4, c0 = tc * 4;
        if (bx < 32) {
#pragma unroll
            for (int i = 0; i < 4; i++)
#pragma unroll
                for (int j = 0; j < 4; j++)
                    QW[(m0 + r0 + i) * DD + j0 + c0 + j] = acc[i][j];
        } else {
#pragma unroll
            for (int i = 0; i < 4; i++)
#pragma unroll
                for (int j = 0; j < 4; j++)
                    g_cwh[(j0 + c0 + j) * NW + (r0 + i)] = __float2half(0.5f * acc[i][j]);
        }
        return;
    }
    colsum_body(w2, DD, g_s1, g_bb, (const float*)nullptr, g_s1w, g_bbw, b - 264, tid);
}

// ================= main HMMA kernel (unchanged from R11 best) =================
#define OFF_A    0          // 8 x 16384 = 131072
#define OFF_B    131072     // 2 x 16384 = 32768
#define OFF_CHAT 163840     // 34816: chat chunk (stride 272B); red at end
#define OFF_CWH  198656     // 18432: cwh chunk (fp16, stride 144B = 72 halves)
#define OFF_META 217088
#define M_MU   0
#define M_IV   128
#define M_U1   256
#define M_U2   768    // [2][512]
#define M_U3   1792   // [2][512]
#define M_LW   2816
#define M_LB   3328
#define SMEM_TC 232448   // == 227 KB opt-in cap

__device__ __forceinline__ void cp_chat(uint32_t sb, int ch, int tid) {
    int j0 = ch * 128;
#pragma unroll
    for (int i = 0; i < 8; i++) {
        int u = tid + i * 256;
        int row = u >> 4, c16 = u & 15;
        cp16(sb + OFF_CHAT + (uint32_t)(row * 272 + c16 * 16),
             (const char*)g_chatT + (size_t)(j0 + row) * 256 + c16 * 16);
    }
#pragma unroll
    for (int i = 0; i < 4; i++) {
        int u = tid + i * 256;
        int row = u >> 3, c16 = u & 7;
        cp16(sb + OFF_CWH + (uint32_t)(row * 144 + c16 * 16),
             (const char*)g_cwh + (size_t)(j0 + row) * 128 + c16 * 16);
    }
}

__device__ __forceinline__ void cp_B(uint32_t sb, int t, int tid) {
    int ch = t >> 3, kc = t & 7;
    int j0 = ch * 128;
    uint32_t bh = sb + OFF_B + (t & 1) * 16384;
    const char* gh = (const char*)g_w2th + (size_t)j0 * 1024 + (size_t)kc * 128;
#pragma unroll
    for (int i = 0; i < 4; i++) {
        int u = tid + i * 256;
        int row = u >> 3, c16 = u & 7;
        uint32_t o = (uint32_t)(row * 128 + c16 * 16);
        cp16(bh + SWZ(o), gh + (size_t)row * 1024 + c16 * 16);
    }
    if (kc == 1) cp_chat(sb, ch, tid);
    asm volatile("cp.async.commit_group;" ::: "memory");
}

__device__ __forceinline__ void buildA(char* smem, int kc, int tid,
                                       const float* meta, int n0) {
    int r = tid >> 1, w = r & 63, rn = r >> 6;
    int kh = (tid & 1) * 32;
    float mu = meta[M_MU + r], iv = meta[M_IV + r];
    const float* Q1p = g_Q1 + (size_t)(n0 + rn) * DD + kc * 64 + kh;
    const float* s1p = g_s1 + kc * 64 + kh;
    const float* bbp = g_bb + kc * 64 + kh;
    const __half* c1p = g_c1h + (size_t)w * DD + kc * 64 + kh;
    char* ah = smem + OFF_A + kc * 16384;
#pragma unroll
    for (int kk = 0; kk < 32; kk += 2) {
        float2 qv = *(const float2*)(Q1p + kk);
        float2 sv = *(const float2*)(s1p + kk);
        float2 bv = *(const float2*)(bbp + kk);
        float2 cf = __half22float2(*(const __half2*)(c1p + kk));
        float ha = iv * (qv.x + cf.x - mu * sv.x) + bv.x;
        float hb = iv * (qv.y + cf.y - mu * sv.y) + bv.y;
        float ga = 0.5f * ha * erff(ha * 0.70710678118654752f);
        float gb = 0.5f * hb * erff(hb * 0.70710678118654752f);
        __half2 hp = __floats2half2_rn(ga, gb);
        uint32_t o = (uint32_t)(r * 128 + (kh + kk) * 2);
        *(__half2*)(ah + SWZ(o)) = hp;
    }
}

__global__ void __launch_bounds__(256, 1)
k_tc7(const float* __restrict__ q, const float* __restrict__ b2,
      const float* __restrict__ ln2w, const float* __restrict__ ln2b,
      float* __restrict__ out) {
    extern __shared__ char smem[];
    const uint32_t sb = smem_u32(smem);
    const int tid = threadIdx.x, lane = tid & 31, wid = tid >> 5;
    const int pair = blockIdx.x;
    const int n0 = pair * 2;
    float* meta = (float*)(smem + OFF_META);
    float* chs = (float*)(smem + OFF_CHAT);
    const __half* cwhs = (const __half*)(smem + OFF_CWH);

    for (int j = tid; j < DD; j += 256) {
        meta[M_U1 + j] = 0.5f * g_s1w[j];
        meta[M_U2 + j]       = 0.5f * g_QW[n0 * DD + j];
        meta[M_U2 + 512 + j] = 0.5f * g_QW[(n0 + 1) * DD + j];
        float hb = b2[j] + 0.5f * g_bbw[j];
        meta[M_U3 + j]       = q[n0 * DD + j] + hb;
        meta[M_U3 + 512 + j] = q[(n0 + 1) * DD + j] + hb;
        meta[M_LW + j] = ln2w[j];
        meta[M_LB + j] = ln2b[j];
    }
    if (tid < 128) {
        int rn = tid >> 6, w = tid & 63;
        float sx  = g_qsum[n0 + rn] + g_csum[w];
        float sxx = g_qssq[n0 + rn] + g_cssq[w];
        float m = sx * (1.f / 1024.f);
        float var = sxx * (1.f / 1024.f) - m * m;
        meta[M_MU + tid] = m;
        meta[M_IV + tid] = rsqrtf(var + LN_EPS);
    }
    __syncthreads();

    buildA(smem, 0, tid, meta, n0);
    cp_chat(sb, 0, tid);
    cp_B(sb, 0, tid);
    __syncthreads();

    const int wm = wid & 3, wn = wid >> 2;
    const int arow = ((lane >> 3) & 1) * 8 + (lane & 7);
    const int acol = lane >> 4;
    const int brow = (lane >> 4) * 8 + (lane & 7);
    const int bcol = (lane >> 3) & 1;
    const int qr = lane >> 2, qc = lane & 3;

    float d[16][4];
#pragma unroll
    for (int i = 0; i < 16; i++)
#pragma unroll
        for (int j = 0; j < 4; j++) d[i][j] = 0.f;
    float pm[4][6];
#pragma unroll
    for (int i = 0; i < 4; i++)
#pragma unroll
        for (int m = 0; m < 6; m++) pm[i][m] = 0.f;

    for (int t = 0; t < 32; t++) {
        const int ch = t >> 3, kc = t & 7;
        if (t < 31) cp_B(sb, t + 1, tid);
        if (t < 31) { asm volatile("cp.async.wait_group 1;" ::: "memory"); }
        else        { asm volatile("cp.async.wait_group 0;" ::: "memory"); }
        __syncthreads();
        uint32_t Ah = sb + OFF_A + kc * 16384;
        uint32_t Bh = sb + OFF_B + (t & 1) * 16384;
#pragma unroll
        for (int s = 0; s < 4; s++) {
            uint32_t ahi[2][4], bhi[4][4];
#pragma unroll
            for (int tm = 0; tm < 2; tm++) {
                uint32_t o = (uint32_t)((32 * wm + 16 * tm + arow) * 128 + (2 * s + acol) * 16);
                ldsm4(ahi[tm], Ah + SWZ(o));
            }
#pragma unroll
            for (int u = 0; u < 4; u++) {
                uint32_t o = (uint32_t)((64 * wn + 16 * u + brow) * 128 + (2 * s + bcol) * 16);
                ldsm4(bhi[u], Bh + SWZ(o));
            }
#pragma unroll
            for (int tm = 0; tm < 2; tm++)
#pragma unroll
                for (int u = 0; u < 4; u++) {
                    mma16816h(d[tm * 8 + 2 * u],     ahi[tm], &bhi[u][0]);
                    mma16816h(d[tm * 8 + 2 * u + 1], ahi[tm], &bhi[u][2]);
                }
        }
        if (ch == 0 && kc < 7) buildA(smem, kc + 1, tid, meta, n0);
        __syncthreads();

        if (kc == 7) {
            const int j0 = ch * 128;
#pragma unroll
            for (int tm = 0; tm < 2; tm++)
#pragma unroll
                for (int h = 0; h < 2; h++) {
                    int row = 32 * wm + 16 * tm + 8 * h + qr;
                    int w = row & 63, rn = row >> 6;
                    float ivr = meta[M_IV + row];
                    float a = -ivr * meta[M_MU + row];
                    float p0 = 0.f, p1 = 0.f, pA = 0.f, pB = 0.f, pC = 0.f, pE = 0.f;
#pragma unroll
                    for (int nt = 0; nt < 8; nt++) {
                        int cl0 = 64 * wn + 8 * nt + qc * 2;
                        int col0 = j0 + cl0;
                        float2 U1 = *(const float2*)&meta[M_U1 + col0];
                        float2 U2 = *(const float2*)&meta[M_U2 + rn * 512 + col0];
                        float2 U3 = *(const float2*)&meta[M_U3 + rn * 512 + col0];
                        float2 LWv = *(const float2*)&meta[M_LW + col0];
                        float2 LBv = *(const float2*)&meta[M_LB + col0];
                        float ch0 = chs[cl0 * 68 + w];
                        float ch1 = chs[(cl0 + 1) * 68 + w];
                        float cw0 = __half2float(cwhs[cl0 * 72 + w]);
                        float cw1 = __half2float(cwhs[(cl0 + 1) * 72 + w]);
                        float v0 = d[tm * 8 + nt][h * 2]     + a * U1.x + ivr * (U2.x + cw0) + U3.x;
                        float v1 = d[tm * 8 + nt][h * 2 + 1] + a * U1.y + ivr * (U2.y + cw1) + U3.y;
                        float vw0 = v0 * LWv.x, vw1 = v1 * LWv.y;
                        p0 += v0 + v1;
                        p1 += v0 * v0 + v1 * v1;
                        pA += vw0 * ch0 + vw1 * ch1;
                        pB += vw0 * vw0 + vw1 * vw1;
                        pC += vw0 * LWv.x + vw1 * LWv.y;
                        pE += vw0 * LBv.x + vw1 * LBv.y;
                    }
                    int i = tm * 2 + h;
                    pm[i][0] += p0; pm[i][1] += p1; pm[i][2] += pA;
                    pm[i][3] += pB; pm[i][4] += pC; pm[i][5] += pE;
                }
            if (t < 31) {
#pragma unroll
                for (int i = 0; i < 16; i++)
#pragma unroll
                    for (int j = 0; j < 4; j++) d[i][j] = 0.f;
            }
        }
    }

    __syncthreads();
    float* sred = (float*)(smem + OFF_CHAT);
#pragma unroll
    for (int tm = 0; tm < 2; tm++)
#pragma unroll
        for (int h = 0; h < 2; h++) {
            int i = tm * 2 + h;
            int row = 32 * wm + 16 * tm + 8 * h + qr;
#pragma unroll
            for (int o = 1; o <= 2; o <<= 1)
#pragma unroll
                for (int m = 0; m < 6; m++)
                    pm[i][m] += __shfl_down_sync(0xffffffffu, pm[i][m], o, 4);
            if (qc == 0) {
                float* rp = sred + (wn * 128 + row) * 8;
#pragma unroll
                for (int m = 0; m < 6; m++) rp[m] = pm[i][m];
            }
        }
    __syncthreads();
    if (tid < 128) {
        int row = tid, w = row & 63, nn = n0 + (row >> 6);
        float m0 = sred[row * 8 + 0] + sred[(128 + row) * 8 + 0];
        float m1 = sred[row * 8 + 1] + sred[(128 + row) * 8 + 1];
        float A  = sred[row * 8 + 2] + sred[(128 + row) * 8 + 2];
        float B  = sred[row * 8 + 3] + sred[(128 + row) * 8 + 3];
        float C  = sred[row * 8 + 4] + sred[(128 + row) * 8 + 4];
        float E  = sred[row * 8 + 5] + sred[(128 + row) * 8 + 5];
        float mu2 = m0 * (1.f / DD);
        float var = m1 * (1.f / DD) - mu2 * mu2;
        float k = rsqrtf(var + LN_EPS);
        float sww = g_scal[0], swb = g_scal[1], sbb = g_scal[2];
        float doty = k * (A - mu2 * g_swc[w]) + g_sbc[w];
        float ny2 = k * k * (B - 2.f * mu2 * C + mu2 * mu2 * sww)
                  + 2.f * k * (E - mu2 * swb) + sbb;
        float ny = sqrtf(fmaxf(ny2, 0.f));
        out[nn * NW + w] = TEMP_SC * doty / fmaxf(ny, 1e-12f);
    }
}

// ================= launch =================
extern "C" void kernel_launch(void* const* d_in, const int* in_sizes, int n_in,
                              void* d_out, int out_size) {
    const float* q    = (const float*)d_in[0];
    const float* cm   = (const float*)d_in[1];
    const float* ln1w = (const float*)d_in[2];
    const float* ln1b = (const float*)d_in[3];
    const float* w1   = (const float*)d_in[4];
    const float* b1   = (const float*)d_in[5];
    const float* w2   = (const float*)d_in[6];
    const float* b2   = (const float*)d_in[7];
    const float* ln2w = (const float*)d_in[8];
    const float* ln2b = (const float*)d_in[9];
    float* out = (float*)d_out;

    float *pQ1, *pC1, *pQW;
    cudaGetSymbolAddress((void**)&pQ1, g_Q1);
    cudaGetSymbolAddress((void**)&pC1, g_C1);
    cudaGetSymbolAddress((void**)&pQW, g_QW);

    cudaFuncSetAttribute(k_tc7, cudaFuncAttributeMaxDynamicSharedMemorySize, SMEM_TC);

    k_phase1<<<2665, 256>>>(q, cm, ln1w, ln1b, b1, w1, w2, ln2w, ln2b, pQ1, pC1);
    k_phase2<<<296, 256>>>(pQ1, pC1, w2, pQW);
    k_tc7<<<NQ / 2, 256, SMEM_TC>>>(q, b2, ln2w, ln2b, out);
}

// round 15
// speedup vs baseline: 1.2541x; 1.1503x over previous
#include <cuda_runtime.h>
#include <cuda_fp16.h>
#include <math.h>
#include <stdint.h>
#include <cstdint>

#define NQ 2048
#define NW 64
#define DD 512
#define D2 1024
#define TEMP_SC 16.0f
#define LN_EPS 1e-5f

// ---------------- scratch ----------------
__device__ float g_Q1[NQ * DD];
__device__ float g_C1[NW * DD];
__device__ float g_s1[DD];
__device__ float g_bb[DD];
__device__ float g_qsum[NQ];
__device__ float g_qssq[NQ];
__device__ float g_csum[NW];
__device__ float g_cssq[NW];
__device__ float g_chatT[DD * NW];     // [j][w]
__device__ float g_swc[NW];
__device__ float g_sbc[NW];
__device__ float g_scal[3];
__device__ __align__(128) __half g_w2th[DD * DD];  // w2^T [j][k] fp16
__device__ __align__(128) __half g_c1h[NW * DD];   // C1 fp16 [w][j]

#define SWZ(o) ((o) ^ (((o) >> 3) & 0x70))

// ================= helpers =================
__device__ __forceinline__ uint32_t smem_u32(const void* p) {
    uint32_t a;
    asm("{ .reg .u64 t; cvta.to.shared.u64 t, %1; cvt.u32.u64 %0, t; }" : "=r"(a) : "l"(p));
    return a;
}
__device__ __forceinline__ void cp16(uint32_t s, const void* g) {
    asm volatile("cp.async.cg.shared.global [%0], [%1], 16;" :: "r"(s), "l"(g));
}
__device__ __forceinline__ void ldsm4(uint32_t* r, uint32_t a) {
    asm volatile("ldmatrix.sync.aligned.m8n8.x4.shared.b16 {%0,%1,%2,%3}, [%4];"
                 : "=r"(r[0]), "=r"(r[1]), "=r"(r[2]), "=r"(r[3]) : "r"(a));
}
__device__ __forceinline__ void mma16816h(float* d, const uint32_t* a, const uint32_t* b) {
    asm volatile("mma.sync.aligned.m16n8k16.row.col.f32.f16.f16.f32 "
                 "{%0,%1,%2,%3}, {%4,%5,%6,%7}, {%8,%9}, {%0,%1,%2,%3};"
                 : "+f"(d[0]), "+f"(d[1]), "+f"(d[2]), "+f"(d[3])
                 : "r"(a[0]), "r"(a[1]), "r"(a[2]), "r"(a[3]), "r"(b[0]), "r"(b[1]));
}

// shared GEMM inner body (64x64 tile, 4x4/thread) — R11-proven
struct GemmSmem {
    __align__(16) float As[16][68];
    __align__(16) float Bs[16][64];
};

__device__ __forceinline__ void gemm_body(GemmSmem* gs, const float* A, int m0,
                                          const float* B, int browoff, int j0,
                                          const float* lnw, int lnoff,
                                          int tid, float acc[4][4]) {
    int tr = tid >> 4, tc = tid & 15;
    int r0 = tr * 4, c0 = tc * 4;
    for (int kc = 0; kc < DD; kc += 16) {
        __syncthreads();
#pragma unroll
        for (int e = 0; e < 4; e++) {
            int idx = tid + e * 256;
            int m = idx >> 4, kk = idx & 15;
            gs->As[kk][m] = A[(m0 + m) * DD + kc + kk] * lnw[lnoff + kc + kk];
        }
#pragma unroll
        for (int e = 0; e < 4; e++) {
            int idx = tid + e * 256;
            int kk = idx >> 6, j = idx & 63;
            gs->Bs[kk][j] = B[(browoff + kc + kk) * DD + j0 + j];
        }
        __syncthreads();
#pragma unroll
        for (int kk = 0; kk < 16; kk++) {
            float4 av = *(const float4*)&gs->As[kk][r0];
            float4 bv = *(const float4*)&gs->Bs[kk][c0];
            acc[0][0] += av.x * bv.x; acc[0][1] += av.x * bv.y; acc[0][2] += av.x * bv.z; acc[0][3] += av.x * bv.w;
            acc[1][0] += av.y * bv.x; acc[1][1] += av.y * bv.y; acc[1][2] += av.y * bv.z; acc[1][3] += av.y * bv.w;
            acc[2][0] += av.z * bv.x; acc[2][1] += av.z * bv.y; acc[2][2] += av.z * bv.z; acc[2][3] += av.z * bv.w;
            acc[3][0] += av.w * bv.x; acc[3][1] += av.w * bv.y; acc[3][2] += av.w * bv.z; acc[3][3] += av.w * bv.w;
        }
    }
}

// ================= phase 1: fold GEMM + stats + w2h + colsum(w1), one launch =================
// blocks [0,264): fold GEMM (33x8); [264,2377): stats; [2377,2633): w2h; [2633,2665): colsum w1
__global__ void k_phase1(const float* __restrict__ q, const float* __restrict__ cm,
                         const float* __restrict__ ln1w, const float* __restrict__ ln1b,
                         const float* __restrict__ b1, const float* __restrict__ w1,
                         const float* __restrict__ w2,
                         const float* __restrict__ ln2w, const float* __restrict__ ln2b,
                         float* __restrict__ Q1, float* __restrict__ C1) {
    int b = blockIdx.x, tid = threadIdx.x;
    int lane = tid & 31, wid = tid >> 5;

    if (b < 264) {
        __shared__ GemmSmem gs;
        int bx = b % 33, by = b / 33;
        int j0 = by * 64;
        const float* A; int m0, rowoff;
        if (bx < 32) { A = q; m0 = bx * 64; rowoff = 0; }
        else         { A = cm; m0 = 0; rowoff = 512; }
        float acc[4][4] = {};
        gemm_body(&gs, A, m0, w1, rowoff, j0, ln1w, rowoff, tid, acc);
        int tr = tid >> 4, tc = tid & 15;
        int r0 = tr * 4, c0 = tc * 4;
        if (bx < 32) {
#pragma unroll
            for (int i = 0; i < 4; i++)
#pragma unroll
                for (int j = 0; j < 4; j++)
                    Q1[(m0 + r0 + i) * DD + j0 + c0 + j] = acc[i][j];
        } else {
#pragma unroll
            for (int i = 0; i < 4; i++)
#pragma unroll
                for (int j = 0; j < 4; j++) {
                    int idx = (r0 + i) * DD + j0 + c0 + j;
                    C1[idx] = acc[i][j];
                    g_c1h[idx] = __float2half(acc[i][j]);
                }
        }
        return;
    }
    if (b < 2377) {
        int sbk = b - 264;
        if (sbk < NQ) {
            float s = 0.f, ss = 0.f;
            for (int j = tid; j < DD; j += 256) { float v = q[sbk * DD + j]; s += v; ss += v * v; }
            __shared__ float sA[8], sB[8];
#pragma unroll
            for (int o = 16; o; o >>= 1) {
                s  += __shfl_down_sync(0xffffffffu, s, o);
                ss += __shfl_down_sync(0xffffffffu, ss, o);
            }
            if (lane == 0) { sA[wid] = s; sB[wid] = ss; }
            __syncthreads();
            if (tid == 0) {
                float a = 0.f, bb = 0.f;
#pragma unroll
                for (int i = 0; i < 8; i++) { a += sA[i]; bb += sB[i]; }
                g_qsum[sbk] = a; g_qssq[sbk] = bb;
            }
        } else if (sbk < 2112) {
            int w = sbk - NQ;
            float s = 0.f, ss = 0.f, sw = 0.f, sb = 0.f;
            for (int j = tid; j < DD; j += 256) {
                float v = cm[w * DD + j];
                s += v; ss += v * v; sw += ln2w[j] * v; sb += ln2b[j] * v;
            }
            __shared__ float sA[8], sB[8], sC[8], sD[8];
            __shared__ float rbc;
#pragma unroll
            for (int o = 16; o; o >>= 1) {
                s  += __shfl_down_sync(0xffffffffu, s,  o);
                ss += __shfl_down_sync(0xffffffffu, ss, o);
                sw += __shfl_down_sync(0xffffffffu, sw, o);
                sb += __shfl_down_sync(0xffffffffu, sb, o);
            }
            if (lane == 0) { sA[wid] = s; sB[wid] = ss; sC[wid] = sw; sD[wid] = sb; }
            __syncthreads();
            if (tid == 0) {
                float a = 0.f, bb = 0.f, c = 0.f, d = 0.f;
#pragma unroll
                for (int i = 0; i < 8; i++) { a += sA[i]; bb += sB[i]; c += sC[i]; d += sD[i]; }
                g_csum[w] = a; g_cssq[w] = bb;
                float r = 1.f / fmaxf(sqrtf(bb), 1e-12f);
                rbc = r; g_swc[w] = r * c; g_sbc[w] = r * d;
            }
            __syncthreads();
            float r = rbc;
            for (int j = tid; j < DD; j += 256)
                g_chatT[j * NW + w] = cm[w * DD + j] * r;
        } else {
            float a = 0.f, bb = 0.f, c = 0.f;
            for (int j = tid; j < DD; j += 256) {
                float w = ln2w[j], z = ln2b[j];
                a += w * w; bb += w * z; c += z * z;
            }
            __shared__ float sA[8], sB[8], sC[8];
#pragma unroll
            for (int o = 16; o; o >>= 1) {
                a  += __shfl_down_sync(0xffffffffu, a,  o);
                bb += __shfl_down_sync(0xffffffffu, bb, o);
                c  += __shfl_down_sync(0xffffffffu, c,  o);
            }
            if (lane == 0) { sA[wid] = a; sB[wid] = bb; sC[wid] = c; }
            __syncthreads();
            if (tid == 0) {
                float x = 0.f, y = 0.f, z = 0.f;
#pragma unroll
                for (int i = 0; i < 8; i++) { x += sA[i]; y += sB[i]; z += sC[i]; }
                g_scal[0] = x; g_scal[1] = y; g_scal[2] = z;
            }
        }
        return;
    }
    if (b < 2633) {
        __shared__ float t[32][33];
        int wb = b - 2377;
        int bx = (wb & 15) * 32, by = (wb >> 4) * 32;
        int tx = tid & 31, ty = tid >> 5;
#pragma unroll
        for (int i = 0; i < 4; i++)
            t[ty + i * 8][tx] = w2[(by + ty + i * 8) * DD + bx + tx];
        __syncthreads();
#pragma unroll
        for (int i = 0; i < 4; i++) {
            int j = bx + ty + i * 8, k = by + tx;
            g_w2th[j * DD + k] = __float2half(t[tx][ty + i * 8]);
        }
        return;
    }
    {
        // colsum w1 -> s1, bb
        __shared__ float sa[16][17], sbm[16][17];
        int blk = b - 2633;
        int jl = tid & 15, ti = tid >> 4;
        int j = blk * 16 + jl;
        float a = 0.f, bb2 = 0.f;
        for (int i = ti; i < D2; i += 16) {
            float wv = w1[i * DD + j];
            a += ln1w[i] * wv; bb2 += ln1b[i] * wv;
        }
        sa[ti][jl] = a; sbm[ti][jl] = bb2;
        __syncthreads();
        if (ti == 0) {
#pragma unroll
            for (int k = 1; k < 16; k++) { a += sa[k][jl]; bb2 += sbm[k][jl]; }
            g_s1[j] = a;
            g_bb[j] = b1[j] + bb2;
        }
    }
}

// ================= main HMMA kernel: full-gelu fp16 A, epilogue v = d + ts =================
#define OFF_A    0          // 8 x 16384 = 131072
#define OFF_B    131072     // 2 x 16384 = 32768
#define OFF_CHAT 163840     // 34816: chat chunk (stride 272B); red at end
#define OFF_META 198656
#define M_MU   0
#define M_IV   128
#define M_U3   256    // [2][512]
#define M_LW   1280
#define M_LB   1792   // -> 2304 floats = 9216 B
#define SMEM_TC 207872

__device__ __forceinline__ void cp_chat(uint32_t sb, int ch, int tid) {
    int j0 = ch * 128;
#pragma unroll
    for (int i = 0; i < 8; i++) {
        int u = tid + i * 256;
        int row = u >> 4, c16 = u & 15;
        cp16(sb + OFF_CHAT + (uint32_t)(row * 272 + c16 * 16),
             (const char*)g_chatT + (size_t)(j0 + row) * 256 + c16 * 16);
    }
}

__device__ __forceinline__ void cp_B(uint32_t sb, int t, int tid) {
    int ch = t >> 3, kc = t & 7;
    int j0 = ch * 128;
    uint32_t bh = sb + OFF_B + (t & 1) * 16384;
    const char* gh = (const char*)g_w2th + (size_t)j0 * 1024 + (size_t)kc * 128;
#pragma unroll
    for (int i = 0; i < 4; i++) {
        int u = tid + i * 256;
        int row = u >> 3, c16 = u & 7;
        uint32_t o = (uint32_t)(row * 128 + c16 * 16);
        cp16(bh + SWZ(o), gh + (size_t)row * 1024 + c16 * 16);
    }
    if (kc == 1) cp_chat(sb, ch, tid);
    asm volatile("cp.async.commit_group;" ::: "memory");
}

// build FULL gelu A subtile kc: gelu(h) = 0.5*h*(1+erf(h/sqrt2)), fp16
__device__ __forceinline__ void buildA(char* smem, int kc, int tid,
                                       const float* meta, int n0) {
    int r = tid >> 1, w = r & 63, rn = r >> 6;
    int kh = (tid & 1) * 32;
    float mu = meta[M_MU + r], iv = meta[M_IV + r];
    const float* Q1p = g_Q1 + (size_t)(n0 + rn) * DD + kc * 64 + kh;
    const float* s1p = g_s1 + kc * 64 + kh;
    const float* bbp = g_bb + kc * 64 + kh;
    const __half* c1p = g_c1h + (size_t)w * DD + kc * 64 + kh;
    char* ah = smem + OFF_A + kc * 16384;
#pragma unroll
    for (int kk = 0; kk < 32; kk += 2) {
        float2 qv = *(const float2*)(Q1p + kk);
        float2 sv = *(const float2*)(s1p + kk);
        float2 bv = *(const float2*)(bbp + kk);
        float2 cf = __half22float2(*(const __half2*)(c1p + kk));
        float ha = iv * (qv.x + cf.x - mu * sv.x) + bv.x;
        float hb = iv * (qv.y + cf.y - mu * sv.y) + bv.y;
        float ga = 0.5f * ha * (1.f + erff(ha * 0.70710678118654752f));
        float gb = 0.5f * hb * (1.f + erff(hb * 0.70710678118654752f));
        __half2 hp = __floats2half2_rn(ga, gb);
        uint32_t o = (uint32_t)(r * 128 + (kh + kk) * 2);
        *(__half2*)(ah + SWZ(o)) = hp;
    }
}

__global__ void __launch_bounds__(256, 1)
k_tc8(const float* __restrict__ q, const float* __restrict__ b2,
      const float* __restrict__ ln2w, const float* __restrict__ ln2b,
      float* __restrict__ out) {
    extern __shared__ char smem[];
    const uint32_t sb = smem_u32(smem);
    const int tid = threadIdx.x, lane = tid & 31, wid = tid >> 5;
    const int pair = blockIdx.x;
    const int n0 = pair * 2;
    float* meta = (float*)(smem + OFF_META);
    float* chs = (float*)(smem + OFF_CHAT);

    for (int j = tid; j < DD; j += 256) {
        float b2j = b2[j];
        meta[M_U3 + j]       = q[n0 * DD + j] + b2j;
        meta[M_U3 + 512 + j] = q[(n0 + 1) * DD + j] + b2j;
        meta[M_LW + j] = ln2w[j];
        meta[M_LB + j] = ln2b[j];
    }
    if (tid < 128) {
        int rn = tid >> 6, w = tid & 63;
        float sx  = g_qsum[n0 + rn] + g_csum[w];
        float sxx = g_qssq[n0 + rn] + g_cssq[w];
        float m = sx * (1.f / 1024.f);
        float var = sxx * (1.f / 1024.f) - m * m;
        meta[M_MU + tid] = m;
        meta[M_IV + tid] = rsqrtf(var + LN_EPS);
    }
    __syncthreads();

    buildA(smem, 0, tid, meta, n0);
    cp_chat(sb, 0, tid);
    cp_B(sb, 0, tid);
    __syncthreads();

    const int wm = wid & 3, wn = wid >> 2;
    const int arow = ((lane >> 3) & 1) * 8 + (lane & 7);
    const int acol = lane >> 4;
    const int brow = (lane >> 4) * 8 + (lane & 7);
    const int bcol = (lane >> 3) & 1;
    const int qr = lane >> 2, qc = lane & 3;

    float d[16][4];
#pragma unroll
    for (int i = 0; i < 16; i++)
#pragma unroll
        for (int j = 0; j < 4; j++) d[i][j] = 0.f;
    float pm[4][6];
#pragma unroll
    for (int i = 0; i < 4; i++)
#pragma unroll
        for (int m = 0; m < 6; m++) pm[i][m] = 0.f;

    for (int t = 0; t < 32; t++) {
        const int ch = t >> 3, kc = t & 7;
        if (t < 31) cp_B(sb, t + 1, tid);
        if (t < 31) { asm volatile("cp.async.wait_group 1;" ::: "memory"); }
        else        { asm volatile("cp.async.wait_group 0;" ::: "memory"); }
        __syncthreads();
        uint32_t Ah = sb + OFF_A + kc * 16384;
        uint32_t Bh = sb + OFF_B + (t & 1) * 16384;
#pragma unroll
        for (int s = 0; s < 4; s++) {
            uint32_t ahi[2][4], bhi[4][4];
#pragma unroll
            for (int tm = 0; tm < 2; tm++) {
                uint32_t o = (uint32_t)((32 * wm + 16 * tm + arow) * 128 + (2 * s + acol) * 16);
                ldsm4(ahi[tm], Ah + SWZ(o));
            }
#pragma unroll
            for (int u = 0; u < 4; u++) {
                uint32_t o = (uint32_t)((64 * wn + 16 * u + brow) * 128 + (2 * s + bcol) * 16);
                ldsm4(bhi[u], Bh + SWZ(o));
            }
#pragma unroll
            for (int tm = 0; tm < 2; tm++)
#pragma unroll
                for (int u = 0; u < 4; u++) {
                    mma16816h(d[tm * 8 + 2 * u],     ahi[tm], &bhi[u][0]);
                    mma16816h(d[tm * 8 + 2 * u + 1], ahi[tm], &bhi[u][2]);
                }
        }
        if (ch == 0 && kc < 7) buildA(smem, kc + 1, tid, meta, n0);
        __syncthreads();

        if (kc == 7) {
            const int j0 = ch * 128;
#pragma unroll
            for (int tm = 0; tm < 2; tm++)
#pragma unroll
                for (int h = 0; h < 2; h++) {
                    int row = 32 * wm + 16 * tm + 8 * h + qr;
                    int w = row & 63, rn = row >> 6;
                    float p0 = 0.f, p1 = 0.f, pA = 0.f, pB = 0.f, pC = 0.f, pE = 0.f;
#pragma unroll
                    for (int nt = 0; nt < 8; nt++) {
                        int cl0 = 64 * wn + 8 * nt + qc * 2;
                        int col0 = j0 + cl0;
                        float2 U3 = *(const float2*)&meta[M_U3 + rn * 512 + col0];
                        float2 LWv = *(const float2*)&meta[M_LW + col0];
                        float2 LBv = *(const float2*)&meta[M_LB + col0];
                        float ch0 = chs[cl0 * 68 + w];
                        float ch1 = chs[(cl0 + 1) * 68 + w];
                        float v0 = d[tm * 8 + nt][h * 2]     + U3.x;
                        float v1 = d[tm * 8 + nt][h * 2 + 1] + U3.y;
                        float vw0 = v0 * LWv.x, vw1 = v1 * LWv.y;
                        p0 += v0 + v1;
                        p1 += v0 * v0 + v1 * v1;
                        pA += vw0 * ch0 + vw1 * ch1;
                        pB += vw0 * vw0 + vw1 * vw1;
                        pC += vw0 * LWv.x + vw1 * LWv.y;
                        pE += vw0 * LBv.x + vw1 * LBv.y;
                    }
                    int i = tm * 2 + h;
                    pm[i][0] += p0; pm[i][1] += p1; pm[i][2] += pA;
                    pm[i][3] += pB; pm[i][4] += pC; pm[i][5] += pE;
                }
            if (t < 31) {
#pragma unroll
                for (int i = 0; i < 16; i++)
#pragma unroll
                    for (int j = 0; j < 4; j++) d[i][j] = 0.f;
            }
        }
    }

    __syncthreads();
    float* sred = (float*)(smem + OFF_CHAT);
#pragma unroll
    for (int tm = 0; tm < 2; tm++)
#pragma unroll
        for (int h = 0; h < 2; h++) {
            int i = tm * 2 + h;
            int row = 32 * wm + 16 * tm + 8 * h + qr;
#pragma unroll
            for (int o = 1; o <= 2; o <<= 1)
#pragma unroll
                for (int m = 0; m < 6; m++)
                    pm[i][m] += __shfl_down_sync(0xffffffffu, pm[i][m], o, 4);
            if (qc == 0) {
                float* rp = sred + (wn * 128 + row) * 8;
#pragma unroll
                for (int m = 0; m < 6; m++) rp[m] = pm[i][m];
            }
        }
    __syncthreads();
    if (tid < 128) {
        int row = tid, w = row & 63, nn = n0 + (row >> 6);
        float m0 = sred[row * 8 + 0] + sred[(128 + row) * 8 + 0];
        float m1 = sred[row * 8 + 1] + sred[(128 + row) * 8 + 1];
        float A  = sred[row * 8 + 2] + sred[(128 + row) * 8 + 2];
        float B  = sred[row * 8 + 3] + sred[(128 + row) * 8 + 3];
        float C  = sred[row * 8 + 4] + sred[(128 + row) * 8 + 4];
        float E  = sred[row * 8 + 5] + sred[(128 + row) * 8 + 5];
        float mu2 = m0 * (1.f / DD);
        float var = m1 * (1.f / DD) - mu2 * mu2;
        float k = rsqrtf(var + LN_EPS);
        float sww = g_scal[0], swb = g_scal[1], sbb = g_scal[2];
        float doty = k * (A - mu2 * g_swc[w]) + g_sbc[w];
        float ny2 = k * k * (B - 2.f * mu2 * C + mu2 * mu2 * sww)
                  + 2.f * k * (E - mu2 * swb) + sbb;
        float ny = sqrtf(fmaxf(ny2, 0.f));
        out[nn * NW + w] = TEMP_SC * doty / fmaxf(ny, 1e-12f);
    }
}

// ================= launch =================
extern "C" void kernel_launch(void* const* d_in, const int* in_sizes, int n_in,
                              void* d_out, int out_size) {
    const float* q    = (const float*)d_in[0];
    const float* cm   = (const float*)d_in[1];
    const float* ln1w = (const float*)d_in[2];
    const float* ln1b = (const float*)d_in[3];
    const float* w1   = (const float*)d_in[4];
    const float* b1   = (const float*)d_in[5];
    const float* w2   = (const float*)d_in[6];
    const float* b2   = (const float*)d_in[7];
    const float* ln2w = (const float*)d_in[8];
    const float* ln2b = (const float*)d_in[9];
    float* out = (float*)d_out;

    float *pQ1, *pC1;
    cudaGetSymbolAddress((void**)&pQ1, g_Q1);
    cudaGetSymbolAddress((void**)&pC1, g_C1);

    cudaFuncSetAttribute(k_tc8, cudaFuncAttributeMaxDynamicSharedMemorySize, SMEM_TC);

    k_phase1<<<2665, 256>>>(q, cm, ln1w, ln1b, b1, w1, w2, ln2w, ln2b, pQ1, pC1);
    k_tc8<<<NQ / 2, 256, SMEM_TC>>>(q, b2, ln2w, ln2b, out);
}

// round 16
// speedup vs baseline: 1.3478x; 1.0747x over previous
#include <cuda_runtime.h>
#include <cuda_fp16.h>
#include <math.h>
#include <stdint.h>
#include <cstdint>

#define NQ 2048
#define NW 64
#define DD 512
#define D2 1024
#define TEMP_SC 16.0f
#define LN_EPS 1e-5f

// ---------------- scratch ----------------
__device__ float g_Q1[NQ * DD];
__device__ float g_C1[NW * DD];
__device__ float g_s1[DD];
__device__ float g_bb[DD];
__device__ float g_qsum[NQ];
__device__ float g_qssq[NQ];
__device__ float g_csum[NW];
__device__ float g_cssq[NW];
__device__ float g_chatT[DD * NW];     // [j][w]
__device__ float g_swc[NW];
__device__ float g_sbc[NW];
__device__ float g_scal[3];
__device__ __align__(128) __half g_w2th[DD * DD];  // w2^T [j][k] fp16
__device__ __align__(128) __half g_c1h[NW * DD];   // C1 fp16 [w][j]

#define SWZ(o) ((o) ^ (((o) >> 3) & 0x70))

// ================= helpers =================
__device__ __forceinline__ uint32_t smem_u32(const void* p) {
    uint32_t a;
    asm("{ .reg .u64 t; cvta.to.shared.u64 t, %1; cvt.u32.u64 %0, t; }" : "=r"(a) : "l"(p));
    return a;
}
__device__ __forceinline__ void cp16(uint32_t s, const void* g) {
    asm volatile("cp.async.cg.shared.global [%0], [%1], 16;" :: "r"(s), "l"(g));
}
__device__ __forceinline__ void ldsm4(uint32_t* r, uint32_t a) {
    asm volatile("ldmatrix.sync.aligned.m8n8.x4.shared.b16 {%0,%1,%2,%3}, [%4];"
                 : "=r"(r[0]), "=r"(r[1]), "=r"(r[2]), "=r"(r[3]) : "r"(a));
}
__device__ __forceinline__ void mma16816h(float* d, const uint32_t* a, const uint32_t* b) {
    asm volatile("mma.sync.aligned.m16n8k16.row.col.f32.f16.f16.f32 "
                 "{%0,%1,%2,%3}, {%4,%5,%6,%7}, {%8,%9}, {%0,%1,%2,%3};"
                 : "+f"(d[0]), "+f"(d[1]), "+f"(d[2]), "+f"(d[3])
                 : "r"(a[0]), "r"(a[1]), "r"(a[2]), "r"(a[3]), "r"(b[0]), "r"(b[1]));
}

// shared GEMM inner body (64x64 tile, 4x4/thread) — R11-proven
struct GemmSmem {
    __align__(16) float As[16][68];
    __align__(16) float Bs[16][64];
};

__device__ __forceinline__ void gemm_body(GemmSmem* gs, const float* A, int m0,
                                          const float* B, int browoff, int j0,
                                          const float* lnw, int lnoff,
                                          int tid, float acc[4][4]) {
    int tr = tid >> 4, tc = tid & 15;
    int r0 = tr * 4, c0 = tc * 4;
    for (int kc = 0; kc < DD; kc += 16) {
        __syncthreads();
#pragma unroll
        for (int e = 0; e < 4; e++) {
            int idx = tid + e * 256;
            int m = idx >> 4, kk = idx & 15;
            gs->As[kk][m] = A[(m0 + m) * DD + kc + kk] * lnw[lnoff + kc + kk];
        }
#pragma unroll
        for (int e = 0; e < 4; e++) {
            int idx = tid + e * 256;
            int kk = idx >> 6, j = idx & 63;
            gs->Bs[kk][j] = B[(browoff + kc + kk) * DD + j0 + j];
        }
        __syncthreads();
#pragma unroll
        for (int kk = 0; kk < 16; kk++) {
            float4 av = *(const float4*)&gs->As[kk][r0];
            float4 bv = *(const float4*)&gs->Bs[kk][c0];
            acc[0][0] += av.x * bv.x; acc[0][1] += av.x * bv.y; acc[0][2] += av.x * bv.z; acc[0][3] += av.x * bv.w;
            acc[1][0] += av.y * bv.x; acc[1][1] += av.y * bv.y; acc[1][2] += av.y * bv.z; acc[1][3] += av.y * bv.w;
            acc[2][0] += av.z * bv.x; acc[2][1] += av.z * bv.y; acc[2][2] += av.z * bv.z; acc[2][3] += av.z * bv.w;
            acc[3][0] += av.w * bv.x; acc[3][1] += av.w * bv.y; acc[3][2] += av.w * bv.z; acc[3][3] += av.w * bv.w;
        }
    }
}

// ================= phase 1 (unchanged from R15) =================
// blocks [0,264): fold GEMM (33x8); [264,2377): stats; [2377,2633): w2h; [2633,2665): colsum w1
__global__ void k_phase1(const float* __restrict__ q, const float* __restrict__ cm,
                         const float* __restrict__ ln1w, const float* __restrict__ ln1b,
                         const float* __restrict__ b1, const float* __restrict__ w1,
                         const float* __restrict__ w2,
                         const float* __restrict__ ln2w, const float* __restrict__ ln2b,
                         float* __restrict__ Q1, float* __restrict__ C1) {
    int b = blockIdx.x, tid = threadIdx.x;
    int lane = tid & 31, wid = tid >> 5;

    if (b < 264) {
        __shared__ GemmSmem gs;
        int bx = b % 33, by = b / 33;
        int j0 = by * 64;
        const float* A; int m0, rowoff;
        if (bx < 32) { A = q; m0 = bx * 64; rowoff = 0; }
        else         { A = cm; m0 = 0; rowoff = 512; }
        float acc[4][4] = {};
        gemm_body(&gs, A, m0, w1, rowoff, j0, ln1w, rowoff, tid, acc);
        int tr = tid >> 4, tc = tid & 15;
        int r0 = tr * 4, c0 = tc * 4;
        if (bx < 32) {
#pragma unroll
            for (int i = 0; i < 4; i++)
#pragma unroll
                for (int j = 0; j < 4; j++)
                    Q1[(m0 + r0 + i) * DD + j0 + c0 + j] = acc[i][j];
        } else {
#pragma unroll
            for (int i = 0; i < 4; i++)
#pragma unroll
                for (int j = 0; j < 4; j++) {
                    int idx = (r0 + i) * DD + j0 + c0 + j;
                    C1[idx] = acc[i][j];
                    g_c1h[idx] = __float2half(acc[i][j]);
                }
        }
        return;
    }
    if (b < 2377) {
        int sbk = b - 264;
        if (sbk < NQ) {
            float s = 0.f, ss = 0.f;
            for (int j = tid; j < DD; j += 256) { float v = q[sbk * DD + j]; s += v; ss += v * v; }
            __shared__ float sA[8], sB[8];
#pragma unroll
            for (int o = 16; o; o >>= 1) {
                s  += __shfl_down_sync(0xffffffffu, s, o);
                ss += __shfl_down_sync(0xffffffffu, ss, o);
            }
            if (lane == 0) { sA[wid] = s; sB[wid] = ss; }
            __syncthreads();
            if (tid == 0) {
                float a = 0.f, bb = 0.f;
#pragma unroll
                for (int i = 0; i < 8; i++) { a += sA[i]; bb += sB[i]; }
                g_qsum[sbk] = a; g_qssq[sbk] = bb;
            }
        } else if (sbk < 2112) {
            int w = sbk - NQ;
            float s = 0.f, ss = 0.f, sw = 0.f, sb = 0.f;
            for (int j = tid; j < DD; j += 256) {
                float v = cm[w * DD + j];
                s += v; ss += v * v; sw += ln2w[j] * v; sb += ln2b[j] * v;
            }
            __shared__ float sA[8], sB[8], sC[8], sD[8];
            __shared__ float rbc;
#pragma unroll
            for (int o = 16; o; o >>= 1) {
                s  += __shfl_down_sync(0xffffffffu, s,  o);
                ss += __shfl_down_sync(0xffffffffu, ss, o);
                sw += __shfl_down_sync(0xffffffffu, sw, o);
                sb += __shfl_down_sync(0xffffffffu, sb, o);
            }
            if (lane == 0) { sA[wid] = s; sB[wid] = ss; sC[wid] = sw; sD[wid] = sb; }
            __syncthreads();
            if (tid == 0) {
                float a = 0.f, bb = 0.f, c = 0.f, d = 0.f;
#pragma unroll
                for (int i = 0; i < 8; i++) { a += sA[i]; bb += sB[i]; c += sC[i]; d += sD[i]; }
                g_csum[w] = a; g_cssq[w] = bb;
                float r = 1.f / fmaxf(sqrtf(bb), 1e-12f);
                rbc = r; g_swc[w] = r * c; g_sbc[w] = r * d;
            }
            __syncthreads();
            float r = rbc;
            for (int j = tid; j < DD; j += 256)
                g_chatT[j * NW + w] = cm[w * DD + j] * r;
        } else {
            float a = 0.f, bb = 0.f, c = 0.f;
            for (int j = tid; j < DD; j += 256) {
                float w = ln2w[j], z = ln2b[j];
                a += w * w; bb += w * z; c += z * z;
            }
            __shared__ float sA[8], sB[8], sC[8];
#pragma unroll
            for (int o = 16; o; o >>= 1) {
                a  += __shfl_down_sync(0xffffffffu, a,  o);
                bb += __shfl_down_sync(0xffffffffu, bb, o);
                c  += __shfl_down_sync(0xffffffffu, c,  o);
            }
            if (lane == 0) { sA[wid] = a; sB[wid] = bb; sC[wid] = c; }
            __syncthreads();
            if (tid == 0) {
                float x = 0.f, y = 0.f, z = 0.f;
#pragma unroll
                for (int i = 0; i < 8; i++) { x += sA[i]; y += sB[i]; z += sC[i]; }
                g_scal[0] = x; g_scal[1] = y; g_scal[2] = z;
            }
        }
        return;
    }
    if (b < 2633) {
        __shared__ float t[32][33];
        int wb = b - 2377;
        int bx = (wb & 15) * 32, by = (wb >> 4) * 32;
        int tx = tid & 31, ty = tid >> 5;
#pragma unroll
        for (int i = 0; i < 4; i++)
            t[ty + i * 8][tx] = w2[(by + ty + i * 8) * DD + bx + tx];
        __syncthreads();
#pragma unroll
        for (int i = 0; i < 4; i++) {
            int j = bx + ty + i * 8, k = by + tx;
            g_w2th[j * DD + k] = __float2half(t[tx][ty + i * 8]);
        }
        return;
    }
    {
        __shared__ float sa[16][17], sbm[16][17];
        int blk = b - 2633;
        int jl = tid & 15, ti = tid >> 4;
        int j = blk * 16 + jl;
        float a = 0.f, bb2 = 0.f;
        for (int i = ti; i < D2; i += 16) {
            float wv = w1[i * DD + j];
            a += ln1w[i] * wv; bb2 += ln1b[i] * wv;
        }
        sa[ti][jl] = a; sbm[ti][jl] = bb2;
        __syncthreads();
        if (ti == 0) {
#pragma unroll
            for (int k = 1; k < 16; k++) { a += sa[k][jl]; bb2 += sbm[k][jl]; }
            g_s1[j] = a;
            g_bb[j] = b1[j] + bb2;
        }
    }
}

// ================= main HMMA kernel: 512 threads, 16 warps, 32x32 warp tile =================
#define TCT 512
#define OFF_A    0          // 8 x 16384 = 131072
#define OFF_B    131072     // 2 x 16384 = 32768
#define OFF_CHAT 163840     // 34816: chat chunk (stride 272B); red (16KB) at end
#define OFF_META 198656
#define M_MU   0
#define M_IV   128
#define M_U3   256    // [2][512]
#define M_LW   1280
#define M_LB   1792   // -> 2304 floats = 9216 B
#define SMEM_TC 207872

__device__ __forceinline__ void cp_chat(uint32_t sb, int ch, int tid) {
    int j0 = ch * 128;
#pragma unroll
    for (int i = 0; i < 4; i++) {
        int u = tid + i * TCT;
        int row = u >> 4, c16 = u & 15;
        cp16(sb + OFF_CHAT + (uint32_t)(row * 272 + c16 * 16),
             (const char*)g_chatT + (size_t)(j0 + row) * 256 + c16 * 16);
    }
}

__device__ __forceinline__ void cp_B(uint32_t sb, int t, int tid) {
    int ch = t >> 3, kc = t & 7;
    int j0 = ch * 128;
    uint32_t bh = sb + OFF_B + (t & 1) * 16384;
    const char* gh = (const char*)g_w2th + (size_t)j0 * 1024 + (size_t)kc * 128;
#pragma unroll
    for (int i = 0; i < 2; i++) {
        int u = tid + i * TCT;
        int row = u >> 3, c16 = u & 7;
        uint32_t o = (uint32_t)(row * 128 + c16 * 16);
        cp16(bh + SWZ(o), gh + (size_t)row * 1024 + c16 * 16);
    }
    if (kc == 1) cp_chat(sb, ch, tid);
    asm volatile("cp.async.commit_group;" ::: "memory");
}

// build FULL gelu A subtile kc (512 threads: 16 values each)
__device__ __forceinline__ void buildA(char* smem, int kc, int tid,
                                       const float* meta, int n0) {
    int r = tid >> 2, w = r & 63, rn = r >> 6;
    int kh = (tid & 3) * 16;
    float mu = meta[M_MU + r], iv = meta[M_IV + r];
    const float* Q1p = g_Q1 + (size_t)(n0 + rn) * DD + kc * 64 + kh;
    const float* s1p = g_s1 + kc * 64 + kh;
    const float* bbp = g_bb + kc * 64 + kh;
    const __half* c1p = g_c1h + (size_t)w * DD + kc * 64 + kh;
    char* ah = smem + OFF_A + kc * 16384;
#pragma unroll
    for (int kk = 0; kk < 16; kk += 2) {
        float2 qv = *(const float2*)(Q1p + kk);
        float2 sv = *(const float2*)(s1p + kk);
        float2 bv = *(const float2*)(bbp + kk);
        float2 cf = __half22float2(*(const __half2*)(c1p + kk));
        float ha = iv * (qv.x + cf.x - mu * sv.x) + bv.x;
        float hb = iv * (qv.y + cf.y - mu * sv.y) + bv.y;
        float ga = 0.5f * ha * (1.f + erff(ha * 0.70710678118654752f));
        float gb = 0.5f * hb * (1.f + erff(hb * 0.70710678118654752f));
        __half2 hp = __floats2half2_rn(ga, gb);
        uint32_t o = (uint32_t)(r * 128 + (kh + kk) * 2);
        *(__half2*)(ah + SWZ(o)) = hp;
    }
}

__global__ void __launch_bounds__(TCT, 1)
k_tc9(const float* __restrict__ q, const float* __restrict__ b2,
      const float* __restrict__ ln2w, const float* __restrict__ ln2b,
      float* __restrict__ out) {
    extern __shared__ char smem[];
    const uint32_t sb = smem_u32(smem);
    const int tid = threadIdx.x, lane = tid & 31, wid = tid >> 5;
    const int pair = blockIdx.x;
    const int n0 = pair * 2;
    float* meta = (float*)(smem + OFF_META);
    float* chs = (float*)(smem + OFF_CHAT);

    for (int j = tid; j < DD; j += TCT) {
        float b2j = b2[j];
        meta[M_U3 + j]       = q[n0 * DD + j] + b2j;
        meta[M_U3 + 512 + j] = q[(n0 + 1) * DD + j] + b2j;
        meta[M_LW + j] = ln2w[j];
        meta[M_LB + j] = ln2b[j];
    }
    if (tid < 128) {
        int rn = tid >> 6, w = tid & 63;
        float sx  = g_qsum[n0 + rn] + g_csum[w];
        float sxx = g_qssq[n0 + rn] + g_cssq[w];
        float m = sx * (1.f / 1024.f);
        float var = sxx * (1.f / 1024.f) - m * m;
        meta[M_MU + tid] = m;
        meta[M_IV + tid] = rsqrtf(var + LN_EPS);
    }
    __syncthreads();

    buildA(smem, 0, tid, meta, n0);
    cp_chat(sb, 0, tid);
    cp_B(sb, 0, tid);
    __syncthreads();

    // warp grid: 4 (rows) x 4 (cols-of-128-chunk)
    const int wm = wid & 3, wn = wid >> 2;
    const int arow = ((lane >> 3) & 1) * 8 + (lane & 7);
    const int acol = lane >> 4;
    const int brow = (lane >> 4) * 8 + (lane & 7);
    const int bcol = (lane >> 3) & 1;
    const int qr = lane >> 2, qc = lane & 3;

    float d[8][4];
#pragma unroll
    for (int i = 0; i < 8; i++)
#pragma unroll
        for (int j = 0; j < 4; j++) d[i][j] = 0.f;
    float pm[4][6];
#pragma unroll
    for (int i = 0; i < 4; i++)
#pragma unroll
        for (int m = 0; m < 6; m++) pm[i][m] = 0.f;

    for (int t = 0; t < 32; t++) {
        const int ch = t >> 3, kc = t & 7;
        if (t < 31) cp_B(sb, t + 1, tid);
        if (t < 31) { asm volatile("cp.async.wait_group 1;" ::: "memory"); }
        else        { asm volatile("cp.async.wait_group 0;" ::: "memory"); }
        __syncthreads();
        uint32_t Ah = sb + OFF_A + kc * 16384;
        uint32_t Bh = sb + OFF_B + (t & 1) * 16384;
#pragma unroll
        for (int s = 0; s < 4; s++) {
            uint32_t ahi[2][4], bhi[2][4];
#pragma unroll
            for (int tm = 0; tm < 2; tm++) {
                uint32_t o = (uint32_t)((32 * wm + 16 * tm + arow) * 128 + (2 * s + acol) * 16);
                ldsm4(ahi[tm], Ah + SWZ(o));
            }
#pragma unroll
            for (int u = 0; u < 2; u++) {
                uint32_t o = (uint32_t)((32 * wn + 16 * u + brow) * 128 + (2 * s + bcol) * 16);
                ldsm4(bhi[u], Bh + SWZ(o));
            }
#pragma unroll
            for (int tm = 0; tm < 2; tm++)
#pragma unroll
                for (int u = 0; u < 2; u++) {
                    mma16816h(d[tm * 4 + u * 2],     ahi[tm], &bhi[u][0]);
                    mma16816h(d[tm * 4 + u * 2 + 1], ahi[tm], &bhi[u][2]);
                }
        }
        if (ch == 0 && kc < 7) buildA(smem, kc + 1, tid, meta, n0);
        __syncthreads();

        if (kc == 7) {
            const int j0 = ch * 128;
#pragma unroll
            for (int tm = 0; tm < 2; tm++)
#pragma unroll
                for (int h = 0; h < 2; h++) {
                    int row = 32 * wm + 16 * tm + 8 * h + qr;
                    int w = row & 63, rn = row >> 6;
                    float p0 = 0.f, p1 = 0.f, pA = 0.f, pB = 0.f, pC = 0.f, pE = 0.f;
#pragma unroll
                    for (int u2 = 0; u2 < 4; u2++) {   // u = u2>>1, half = u2&1
                        int cl0 = 32 * wn + u2 * 8 + qc * 2;
                        int col0 = j0 + cl0;
                        float2 U3 = *(const float2*)&meta[M_U3 + rn * 512 + col0];
                        float2 LWv = *(const float2*)&meta[M_LW + col0];
                        float2 LBv = *(const float2*)&meta[M_LB + col0];
                        float ch0 = chs[cl0 * 68 + w];
                        float ch1 = chs[(cl0 + 1) * 68 + w];
                        float v0 = d[tm * 4 + u2][h * 2]     + U3.x;
                        float v1 = d[tm * 4 + u2][h * 2 + 1] + U3.y;
                        float vw0 = v0 * LWv.x, vw1 = v1 * LWv.y;
                        p0 += v0 + v1;
                        p1 += v0 * v0 + v1 * v1;
                        pA += vw0 * ch0 + vw1 * ch1;
                        pB += vw0 * vw0 + vw1 * vw1;
                        pC += vw0 * LWv.x + vw1 * LWv.y;
                        pE += vw0 * LBv.x + vw1 * LBv.y;
                    }
                    int i = tm * 2 + h;
                    pm[i][0] += p0; pm[i][1] += p1; pm[i][2] += pA;
                    pm[i][3] += pB; pm[i][4] += pC; pm[i][5] += pE;
                }
            if (t < 31) {
#pragma unroll
                for (int i = 0; i < 8; i++)
#pragma unroll
                    for (int j = 0; j < 4; j++) d[i][j] = 0.f;
            }
        }
    }

    // ---- final reduce (red aliases CHAT region; 4 wn groups) ----
    __syncthreads();
    float* sred = (float*)(smem + OFF_CHAT);
#pragma unroll
    for (int tm = 0; tm < 2; tm++)
#pragma unroll
        for (int h = 0; h < 2; h++) {
            int i = tm * 2 + h;
            int row = 32 * wm + 16 * tm + 8 * h + qr;
#pragma unroll
            for (int o = 1; o <= 2; o <<= 1)
#pragma unroll
                for (int m = 0; m < 6; m++)
                    pm[i][m] += __shfl_down_sync(0xffffffffu, pm[i][m], o, 4);
            if (qc == 0) {
                float* rp = sred + (wn * 128 + row) * 8;
#pragma unroll
                for (int m = 0; m < 6; m++) rp[m] = pm[i][m];
            }
        }
    __syncthreads();
    if (tid < 128) {
        int row = tid, w = row & 63, nn = n0 + (row >> 6);
        float mm[6];
#pragma unroll
        for (int m = 0; m < 6; m++) {
            float v = 0.f;
#pragma unroll
            for (int g = 0; g < 4; g++) v += sred[(g * 128 + row) * 8 + m];
            mm[m] = v;
        }
        float mu2 = mm[0] * (1.f / DD);
        float var = mm[1] * (1.f / DD) - mu2 * mu2;
        float k = rsqrtf(var + LN_EPS);
        float sww = g_scal[0], swb = g_scal[1], sbb = g_scal[2];
        float doty = k * (mm[2] - mu2 * g_swc[w]) + g_sbc[w];
        float ny2 = k * k * (mm[3] - 2.f * mu2 * mm[4] + mu2 * mu2 * sww)
                  + 2.f * k * (mm[5] - mu2 * swb) + sbb;
        float ny = sqrtf(fmaxf(ny2, 0.f));
        out[nn * NW + w] = TEMP_SC * doty / fmaxf(ny, 1e-12f);
    }
}

// ================= launch =================
extern "C" void kernel_launch(void* const* d_in, const int* in_sizes, int n_in,
                              void* d_out, int out_size) {
    const float* q    = (const float*)d_in[0];
    const float* cm   = (const float*)d_in[1];
    const float* ln1w = (const float*)d_in[2];
    const float* ln1b = (const float*)d_in[3];
    const float* w1   = (const float*)d_in[4];
    const float* b1   = (const float*)d_in[5];
    const float* w2   = (const float*)d_in[6];
    const float* b2   = (const float*)d_in[7];
    const float* ln2w = (const float*)d_in[8];
    const float* ln2b = (const float*)d_in[9];
    float* out = (float*)d_out;

    float *pQ1, *pC1;
    cudaGetSymbolAddress((void**)&pQ1, g_Q1);
    cudaGetSymbolAddress((void**)&pC1, g_C1);

    cudaFuncSetAttribute(k_tc9, cudaFuncAttributeMaxDynamicSharedMemorySize, SMEM_TC);

    k_phase1<<<2665, 256>>>(q, cm, ln1w, ln1b, b1, w1, w2, ln2w, ln2b, pQ1, pC1);
    k_tc9<<<NQ / 2, TCT, SMEM_TC>>>(q, b2, ln2w, ln2b, out);
}

// round 17
// speedup vs baseline: 1.3902x; 1.0315x over previous
#include <cuda_runtime.h>
#include <cuda_fp16.h>
#include <math.h>
#include <stdint.h>
#include <cstdint>

#define NQ 2048
#define NW 64
#define DD 512
#define D2 1024
#define TEMP_SC 16.0f
#define LN_EPS 1e-5f

// ---------------- scratch ----------------
__device__ float g_Q1[NQ * DD];
__device__ float g_C1[NW * DD];
__device__ float g_s1[DD];
__device__ float g_bb[DD];
__device__ float g_qsum[NQ];
__device__ float g_qssq[NQ];
__device__ float g_csum[NW];
__device__ float g_cssq[NW];
__device__ float g_chatT[DD * NW];     // [j][w]
__device__ float g_swc[NW];
__device__ float g_sbc[NW];
__device__ float g_scal[3];
__device__ __align__(128) __half g_w2th[DD * DD];  // w2^T [j][k] fp16
__device__ __align__(128) __half g_c1h[NW * DD];   // C1 fp16 [w][j]

#define SWZ(o) ((o) ^ (((o) >> 3) & 0x70))

// ================= helpers =================
__device__ __forceinline__ uint32_t smem_u32(const void* p) {
    uint32_t a;
    asm("{ .reg .u64 t; cvta.to.shared.u64 t, %1; cvt.u32.u64 %0, t; }" : "=r"(a) : "l"(p));
    return a;
}
__device__ __forceinline__ void cp16(uint32_t s, const void* g) {
    asm volatile("cp.async.cg.shared.global [%0], [%1], 16;" :: "r"(s), "l"(g));
}
__device__ __forceinline__ void ldsm4(uint32_t* r, uint32_t a) {
    asm volatile("ldmatrix.sync.aligned.m8n8.x4.shared.b16 {%0,%1,%2,%3}, [%4];"
                 : "=r"(r[0]), "=r"(r[1]), "=r"(r[2]), "=r"(r[3]) : "r"(a));
}
__device__ __forceinline__ void mma16816h(float* d, const uint32_t* a, const uint32_t* b) {
    asm volatile("mma.sync.aligned.m16n8k16.row.col.f32.f16.f16.f32 "
                 "{%0,%1,%2,%3}, {%4,%5,%6,%7}, {%8,%9}, {%0,%1,%2,%3};"
                 : "+f"(d[0]), "+f"(d[1]), "+f"(d[2]), "+f"(d[3])
                 : "r"(a[0]), "r"(a[1]), "r"(a[2]), "r"(a[3]), "r"(b[0]), "r"(b[1]));
}

// shared GEMM inner body (64x64 tile, 4x4/thread) — R11-proven
struct GemmSmem {
    __align__(16) float As[16][68];
    __align__(16) float Bs[16][64];
};

__device__ __forceinline__ void gemm_body(GemmSmem* gs, const float* A, int m0,
                                          const float* B, int browoff, int j0,
                                          const float* lnw, int lnoff,
                                          int tid, float acc[4][4]) {
    int tr = tid >> 4, tc = tid & 15;
    int r0 = tr * 4, c0 = tc * 4;
    for (int kc = 0; kc < DD; kc += 16) {
        __syncthreads();
#pragma unroll
        for (int e = 0; e < 4; e++) {
            int idx = tid + e * 256;
            int m = idx >> 4, kk = idx & 15;
            gs->As[kk][m] = A[(m0 + m) * DD + kc + kk] * lnw[lnoff + kc + kk];
        }
#pragma unroll
        for (int e = 0; e < 4; e++) {
            int idx = tid + e * 256;
            int kk = idx >> 6, j = idx & 63;
            gs->Bs[kk][j] = B[(browoff + kc + kk) * DD + j0 + j];
        }
        __syncthreads();
#pragma unroll
        for (int kk = 0; kk < 16; kk++) {
            float4 av = *(const float4*)&gs->As[kk][r0];
            float4 bv = *(const float4*)&gs->Bs[kk][c0];
            acc[0][0] += av.x * bv.x; acc[0][1] += av.x * bv.y; acc[0][2] += av.x * bv.z; acc[0][3] += av.x * bv.w;
            acc[1][0] += av.y * bv.x; acc[1][1] += av.y * bv.y; acc[1][2] += av.y * bv.z; acc[1][3] += av.y * bv.w;
            acc[2][0] += av.z * bv.x; acc[2][1] += av.z * bv.y; acc[2][2] += av.z * bv.z; acc[2][3] += av.z * bv.w;
            acc[3][0] += av.w * bv.x; acc[3][1] += av.w * bv.y; acc[3][2] += av.w * bv.z; acc[3][3] += av.w * bv.w;
        }
    }
}

// ================= phase 1 (unchanged) =================
__global__ void k_phase1(const float* __restrict__ q, const float* __restrict__ cm,
                         const float* __restrict__ ln1w, const float* __restrict__ ln1b,
                         const float* __restrict__ b1, const float* __restrict__ w1,
                         const float* __restrict__ w2,
                         const float* __restrict__ ln2w, const float* __restrict__ ln2b,
                         float* __restrict__ Q1, float* __restrict__ C1) {
    int b = blockIdx.x, tid = threadIdx.x;
    int lane = tid & 31, wid = tid >> 5;

    if (b < 264) {
        __shared__ GemmSmem gs;
        int bx = b % 33, by = b / 33;
        int j0 = by * 64;
        const float* A; int m0, rowoff;
        if (bx < 32) { A = q; m0 = bx * 64; rowoff = 0; }
        else         { A = cm; m0 = 0; rowoff = 512; }
        float acc[4][4] = {};
        gemm_body(&gs, A, m0, w1, rowoff, j0, ln1w, rowoff, tid, acc);
        int tr = tid >> 4, tc = tid & 15;
        int r0 = tr * 4, c0 = tc * 4;
        if (bx < 32) {
#pragma unroll
            for (int i = 0; i < 4; i++)
#pragma unroll
                for (int j = 0; j < 4; j++)
                    Q1[(m0 + r0 + i) * DD + j0 + c0 + j] = acc[i][j];
        } else {
#pragma unroll
            for (int i = 0; i < 4; i++)
#pragma unroll
                for (int j = 0; j < 4; j++) {
                    int idx = (r0 + i) * DD + j0 + c0 + j;
                    C1[idx] = acc[i][j];
                    g_c1h[idx] = __float2half(acc[i][j]);
                }
        }
        return;
    }
    if (b < 2377) {
        int sbk = b - 264;
        if (sbk < NQ) {
            float s = 0.f, ss = 0.f;
            for (int j = tid; j < DD; j += 256) { float v = q[sbk * DD + j]; s += v; ss += v * v; }
            __shared__ float sA[8], sB[8];
#pragma unroll
            for (int o = 16; o; o >>= 1) {
                s  += __shfl_down_sync(0xffffffffu, s, o);
                ss += __shfl_down_sync(0xffffffffu, ss, o);
            }
            if (lane == 0) { sA[wid] = s; sB[wid] = ss; }
            __syncthreads();
            if (tid == 0) {
                float a = 0.f, bb = 0.f;
#pragma unroll
                for (int i = 0; i < 8; i++) { a += sA[i]; bb += sB[i]; }
                g_qsum[sbk] = a; g_qssq[sbk] = bb;
            }
        } else if (sbk < 2112) {
            int w = sbk - NQ;
            float s = 0.f, ss = 0.f, sw = 0.f, sb = 0.f;
            for (int j = tid; j < DD; j += 256) {
                float v = cm[w * DD + j];
                s += v; ss += v * v; sw += ln2w[j] * v; sb += ln2b[j] * v;
            }
            __shared__ float sA[8], sB[8], sC[8], sD[8];
            __shared__ float rbc;
#pragma unroll
            for (int o = 16; o; o >>= 1) {
                s  += __shfl_down_sync(0xffffffffu, s,  o);
                ss += __shfl_down_sync(0xffffffffu, ss, o);
                sw += __shfl_down_sync(0xffffffffu, sw, o);
                sb += __shfl_down_sync(0xffffffffu, sb, o);
            }
            if (lane == 0) { sA[wid] = s; sB[wid] = ss; sC[wid] = sw; sD[wid] = sb; }
            __syncthreads();
            if (tid == 0) {
                float a = 0.f, bb = 0.f, c = 0.f, d = 0.f;
#pragma unroll
                for (int i = 0; i < 8; i++) { a += sA[i]; bb += sB[i]; c += sC[i]; d += sD[i]; }
                g_csum[w] = a; g_cssq[w] = bb;
                float r = 1.f / fmaxf(sqrtf(bb), 1e-12f);
                rbc = r; g_swc[w] = r * c; g_sbc[w] = r * d;
            }
            __syncthreads();
            float r = rbc;
            for (int j = tid; j < DD; j += 256)
                g_chatT[j * NW + w] = cm[w * DD + j] * r;
        } else {
            float a = 0.f, bb = 0.f, c = 0.f;
            for (int j = tid; j < DD; j += 256) {
                float w = ln2w[j], z = ln2b[j];
                a += w * w; bb += w * z; c += z * z;
            }
            __shared__ float sA[8], sB[8], sC[8];
#pragma unroll
            for (int o = 16; o; o >>= 1) {
                a  += __shfl_down_sync(0xffffffffu, a,  o);
                bb += __shfl_down_sync(0xffffffffu, bb, o);
                c  += __shfl_down_sync(0xffffffffu, c,  o);
            }
            if (lane == 0) { sA[wid] = a; sB[wid] = bb; sC[wid] = c; }
            __syncthreads();
            if (tid == 0) {
                float x = 0.f, y = 0.f, z = 0.f;
#pragma unroll
                for (int i = 0; i < 8; i++) { x += sA[i]; y += sB[i]; z += sC[i]; }
                g_scal[0] = x; g_scal[1] = y; g_scal[2] = z;
            }
        }
        return;
    }
    if (b < 2633) {
        __shared__ float t[32][33];
        int wb = b - 2377;
        int bx = (wb & 15) * 32, by = (wb >> 4) * 32;
        int tx = tid & 31, ty = tid >> 5;
#pragma unroll
        for (int i = 0; i < 4; i++)
            t[ty + i * 8][tx] = w2[(by + ty + i * 8) * DD + bx + tx];
        __syncthreads();
#pragma unroll
        for (int i = 0; i < 4; i++) {
            int j = bx + ty + i * 8, k = by + tx;
            g_w2th[j * DD + k] = __float2half(t[tx][ty + i * 8]);
        }
        return;
    }
    {
        __shared__ float sa[16][17], sbm[16][17];
        int blk = b - 2633;
        int jl = tid & 15, ti = tid >> 4;
        int j = blk * 16 + jl;
        float a = 0.f, bb2 = 0.f;
        for (int i = ti; i < D2; i += 16) {
            float wv = w1[i * DD + j];
            a += ln1w[i] * wv; bb2 += ln1b[i] * wv;
        }
        sa[ti][jl] = a; sbm[ti][jl] = bb2;
        __syncthreads();
        if (ti == 0) {
#pragma unroll
            for (int k = 1; k < 16; k++) { a += sa[k][jl]; bb2 += sbm[k][jl]; }
            g_s1[j] = a;
            g_bb[j] = b1[j] + bb2;
        }
    }
}

// ================= main HMMA kernel: 512 thr, 1 sync/step, pipelined fragments =================
#define TCT 512
#define OFF_A    0          // 8 x 16384 = 131072
#define OFF_B    131072     // 2 x 16384 = 32768
#define OFF_CHAT 163840     // 34816: chat chunk (stride 272B); red at end
#define OFF_META 198656
#define M_MU   0
#define M_IV   128
#define M_U3   256    // [2][512]
#define M_LW   1280
#define M_LB   1792   // -> 2304 floats = 9216 B
#define SMEM_TC 207872

__device__ __forceinline__ void cp_chat(uint32_t sb, int ch, int tid) {
    int j0 = ch * 128;
#pragma unroll
    for (int i = 0; i < 4; i++) {
        int u = tid + i * TCT;
        int row = u >> 4, c16 = u & 15;
        cp16(sb + OFF_CHAT + (uint32_t)(row * 272 + c16 * 16),
             (const char*)g_chatT + (size_t)(j0 + row) * 256 + c16 * 16);
    }
}

__device__ __forceinline__ void cp_B(uint32_t sb, int t, int tid) {
    int ch = t >> 3, kc = t & 7;
    int j0 = ch * 128;
    uint32_t bh = sb + OFF_B + (t & 1) * 16384;
    const char* gh = (const char*)g_w2th + (size_t)j0 * 1024 + (size_t)kc * 128;
#pragma unroll
    for (int i = 0; i < 2; i++) {
        int u = tid + i * TCT;
        int row = u >> 3, c16 = u & 7;
        uint32_t o = (uint32_t)(row * 128 + c16 * 16);
        cp16(bh + SWZ(o), gh + (size_t)row * 1024 + c16 * 16);
    }
    if (kc == 1) cp_chat(sb, ch, tid);
    asm volatile("cp.async.commit_group;" ::: "memory");
}

// build FULL gelu A subtile kc (512 threads: 16 values each)
__device__ __forceinline__ void buildA(char* smem, int kc, int tid,
                                       const float* meta, int n0) {
    int r = tid >> 2, w = r & 63, rn = r >> 6;
    int kh = (tid & 3) * 16;
    float mu = meta[M_MU + r], iv = meta[M_IV + r];
    const float* Q1p = g_Q1 + (size_t)(n0 + rn) * DD + kc * 64 + kh;
    const float* s1p = g_s1 + kc * 64 + kh;
    const float* bbp = g_bb + kc * 64 + kh;
    const __half* c1p = g_c1h + (size_t)w * DD + kc * 64 + kh;
    char* ah = smem + OFF_A + kc * 16384;
#pragma unroll
    for (int kk = 0; kk < 16; kk += 2) {
        float2 qv = *(const float2*)(Q1p + kk);
        float2 sv = *(const float2*)(s1p + kk);
        float2 bv = *(const float2*)(bbp + kk);
        float2 cf = __half22float2(*(const __half2*)(c1p + kk));
        float ha = iv * (qv.x + cf.x - mu * sv.x) + bv.x;
        float hb = iv * (qv.y + cf.y - mu * sv.y) + bv.y;
        float ga = 0.5f * ha * (1.f + erff(ha * 0.70710678118654752f));
        float gb = 0.5f * hb * (1.f + erff(hb * 0.70710678118654752f));
        __half2 hp = __floats2half2_rn(ga, gb);
        uint32_t o = (uint32_t)(r * 128 + (kh + kk) * 2);
        *(__half2*)(ah + SWZ(o)) = hp;
    }
}

__global__ void __launch_bounds__(TCT, 1)
k_tc10(const float* __restrict__ q, const float* __restrict__ b2,
       const float* __restrict__ ln2w, const float* __restrict__ ln2b,
       float* __restrict__ out) {
    extern __shared__ char smem[];
    const uint32_t sb = smem_u32(smem);
    const int tid = threadIdx.x, lane = tid & 31, wid = tid >> 5;
    const int pair = blockIdx.x;
    const int n0 = pair * 2;
    float* meta = (float*)(smem + OFF_META);
    float* chs = (float*)(smem + OFF_CHAT);

    for (int j = tid; j < DD; j += TCT) {
        float b2j = b2[j];
        meta[M_U3 + j]       = q[n0 * DD + j] + b2j;
        meta[M_U3 + 512 + j] = q[(n0 + 1) * DD + j] + b2j;
        meta[M_LW + j] = ln2w[j];
        meta[M_LB + j] = ln2b[j];
    }
    if (tid < 128) {
        int rn = tid >> 6, w = tid & 63;
        float sx  = g_qsum[n0 + rn] + g_csum[w];
        float sxx = g_qssq[n0 + rn] + g_cssq[w];
        float m = sx * (1.f / 1024.f);
        float var = sxx * (1.f / 1024.f) - m * m;
        meta[M_MU + tid] = m;
        meta[M_IV + tid] = rsqrtf(var + LN_EPS);
    }
    __syncthreads();

    buildA(smem, 0, tid, meta, n0);
    cp_chat(sb, 0, tid);
    cp_B(sb, 0, tid);

    const int wm = wid & 3, wn = wid >> 2;
    const int arow = ((lane >> 3) & 1) * 8 + (lane & 7);
    const int acol = lane >> 4;
    const int brow = (lane >> 4) * 8 + (lane & 7);
    const int bcol = (lane >> 3) & 1;
    const int qr = lane >> 2, qc = lane & 3;

    float d[8][4];
#pragma unroll
    for (int i = 0; i < 8; i++)
#pragma unroll
        for (int j = 0; j < 4; j++) d[i][j] = 0.f;
    float pm[4][6];
#pragma unroll
    for (int i = 0; i < 4; i++)
#pragma unroll
        for (int m = 0; m < 6; m++) pm[i][m] = 0.f;

    for (int t = 0; t < 32; t++) {
        const int ch = t >> 3, kc = t & 7;
        // wait for B(t) (the only outstanding group), then one sync
        asm volatile("cp.async.wait_group 0;" ::: "memory");
        __syncthreads();
        // prefetch B(t+1): writes buf (t+1)&1, whose readers (step t-1) are behind the sync
        if (t < 31) cp_B(sb, t + 1, tid);

        uint32_t Ah = sb + OFF_A + kc * 16384;
        uint32_t Bh = sb + OFF_B + (t & 1) * 16384;

        // software-pipelined fragment loop
        uint32_t ahi[2][2][4], bhi[2][2][4];
#pragma unroll
        for (int tm = 0; tm < 2; tm++) {
            uint32_t o = (uint32_t)((32 * wm + 16 * tm + arow) * 128 + acol * 16);
            ldsm4(ahi[0][tm], Ah + SWZ(o));
        }
#pragma unroll
        for (int u = 0; u < 2; u++) {
            uint32_t o = (uint32_t)((32 * wn + 16 * u + brow) * 128 + bcol * 16);
            ldsm4(bhi[0][u], Bh + SWZ(o));
        }
#pragma unroll
        for (int s = 0; s < 4; s++) {
            int p = s & 1;
            if (s < 3) {
                int pn = p ^ 1;
#pragma unroll
                for (int tm = 0; tm < 2; tm++) {
                    uint32_t o = (uint32_t)((32 * wm + 16 * tm + arow) * 128 + (2 * (s + 1) + acol) * 16);
                    ldsm4(ahi[pn][tm], Ah + SWZ(o));
                }
#pragma unroll
                for (int u = 0; u < 2; u++) {
                    uint32_t o = (uint32_t)((32 * wn + 16 * u + brow) * 128 + (2 * (s + 1) + bcol) * 16);
                    ldsm4(bhi[pn][u], Bh + SWZ(o));
                }
            }
#pragma unroll
            for (int tm = 0; tm < 2; tm++)
#pragma unroll
                for (int u = 0; u < 2; u++) {
                    mma16816h(d[tm * 4 + u * 2],     ahi[p][tm], &bhi[p][u][0]);
                    mma16816h(d[tm * 4 + u * 2 + 1], ahi[p][tm], &bhi[p][u][2]);
                }
        }
        if (ch == 0 && kc < 7) buildA(smem, kc + 1, tid, meta, n0);

        if (kc == 7) {
            const int j0 = ch * 128;
#pragma unroll
            for (int tm = 0; tm < 2; tm++)
#pragma unroll
                for (int h = 0; h < 2; h++) {
                    int row = 32 * wm + 16 * tm + 8 * h + qr;
                    int w = row & 63, rn = row >> 6;
                    float p0 = 0.f, p1 = 0.f, pA = 0.f, pB = 0.f, pC = 0.f, pE = 0.f;
#pragma unroll
                    for (int u2 = 0; u2 < 4; u2++) {
                        int cl0 = 32 * wn + u2 * 8 + qc * 2;
                        int col0 = j0 + cl0;
                        float2 U3 = *(const float2*)&meta[M_U3 + rn * 512 + col0];
                        float2 LWv = *(const float2*)&meta[M_LW + col0];
                        float2 LBv = *(const float2*)&meta[M_LB + col0];
                        float ch0 = chs[cl0 * 68 + w];
                        float ch1 = chs[(cl0 + 1) * 68 + w];
                        float v0 = d[tm * 4 + u2][h * 2]     + U3.x;
                        float v1 = d[tm * 4 + u2][h * 2 + 1] + U3.y;
                        float vw0 = v0 * LWv.x, vw1 = v1 * LWv.y;
                        p0 += v0 + v1;
                        p1 += v0 * v0 + v1 * v1;
                        pA += vw0 * ch0 + vw1 * ch1;
                        pB += vw0 * vw0 + vw1 * vw1;
                        pC += vw0 * LWv.x + vw1 * LWv.y;
                        pE += vw0 * LBv.x + vw1 * LBv.y;
                    }
                    int i = tm * 2 + h;
                    pm[i][0] += p0; pm[i][1] += p1; pm[i][2] += pA;
                    pm[i][3] += pB; pm[i][4] += pC; pm[i][5] += pE;
                }
            if (t < 31) {
#pragma unroll
                for (int i = 0; i < 8; i++)
#pragma unroll
                    for (int j = 0; j < 4; j++) d[i][j] = 0.f;
            }
        }
    }

    // ---- final reduce (red aliases CHAT region; 4 wn groups) ----
    __syncthreads();
    float* sred = (float*)(smem + OFF_CHAT);
#pragma unroll
    for (int tm = 0; tm < 2; tm++)
#pragma unroll
        for (int h = 0; h < 2; h++) {
            int i = tm * 2 + h;
            int row = 32 * wm + 16 * tm + 8 * h + qr;
#pragma unroll
            for (int o = 1; o <= 2; o <<= 1)
#pragma unroll
                for (int m = 0; m < 6; m++)
                    pm[i][m] += __shfl_down_sync(0xffffffffu, pm[i][m], o, 4);
            if (qc == 0) {
                float* rp = sred + (wn * 128 + row) * 8;
#pragma unroll
                for (int m = 0; m < 6; m++) rp[m] = pm[i][m];
            }
        }
    __syncthreads();
    if (tid < 128) {
        int row = tid, w = row & 63, nn = n0 + (row >> 6);
        float mm[6];
#pragma unroll
        for (int m = 0; m < 6; m++) {
            float v = 0.f;
#pragma unroll
            for (int g = 0; g < 4; g++) v += sred[(g * 128 + row) * 8 + m];
            mm[m] = v;
        }
        float mu2 = mm[0] * (1.f / DD);
        float var = mm[1] * (1.f / DD) - mu2 * mu2;
        float k = rsqrtf(var + LN_EPS);
        float sww = g_scal[0], swb = g_scal[1], sbb = g_scal[2];
        float doty = k * (mm[2] - mu2 * g_swc[w]) + g_sbc[w];
        float ny2 = k * k * (mm[3] - 2.f * mu2 * mm[4] + mu2 * mu2 * sww)
                  + 2.f * k * (mm[5] - mu2 * swb) + sbb;
        float ny = sqrtf(fmaxf(ny2, 0.f));
        out[nn * NW + w] = TEMP_SC * doty / fmaxf(ny, 1e-12f);
    }
}

// ================= launch =================
extern "C" void kernel_launch(void* const* d_in, const int* in_sizes, int n_in,
                              void* d_out, int out_size) {
    const float* q    = (const float*)d_in[0];
    const float* cm   = (const float*)d_in[1];
    const float* ln1w = (const float*)d_in[2];
    const float* ln1b = (const float*)d_in[3];
    const float* w1   = (const float*)d_in[4];
    const float* b1   = (const float*)d_in[5];
    const float* w2   = (const float*)d_in[6];
    const float* b2   = (const float*)d_in[7];
    const float* ln2w = (const float*)d_in[8];
    const float* ln2b = (const float*)d_in[9];
    float* out = (float*)d_out;

    float *pQ1, *pC1;
    cudaGetSymbolAddress((void**)&pQ1, g_Q1);
    cudaGetSymbolAddress((void**)&pC1, g_C1);

    cudaFuncSetAttribute(k_tc10, cudaFuncAttributeMaxDynamicSharedMemorySize, SMEM_TC);

    k_phase1<<<2665, 256>>>(q, cm, ln1w, ln1b, b1, w1, w2, ln2w, ln2b, pQ1, pC1);
    k_tc10<<<NQ / 2, TCT, SMEM_TC>>>(q, b2, ln2w, ln2b, out);
}